// round 11
// baseline (speedup 1.0000x reference)
#include <cuda_runtime.h>
#include <cuda_bf16.h>
#include <cstdint>
#include <math.h>

// ---------------- problem constants ----------------
#define BBATCH 4
#define TT 2048
#define DD 1024
#define HH 16
#define PP 64
#define FFD 4096
#define ROWS (BBATCH*TT)          // 8192

typedef __nv_bfloat16 bf16;

#define SMEM_SWIZZLE_64B(off)  ((off) ^ (((off) >> 3) & 0x30))

__device__ __forceinline__ uint32_t smem_to_u32(const void* p) {
    uint32_t a;
    asm("{ .reg .u64 t; cvta.to.shared.u64 t, %1; cvt.u32.u64 %0, t; }" : "=r"(a) : "l"(p));
    return a;
}
__device__ __forceinline__ void cp16(uint32_t s, const void* g) {
    asm volatile("cp.async.cg.shared.global [%0], [%1], 16;" :: "r"(s), "l"(g));
}
#define CP_COMMIT() asm volatile("cp.async.commit_group;" ::: "memory")
#define CP_WAIT1()  asm volatile("cp.async.wait_group 1;" ::: "memory")

__device__ __forceinline__ void ldsm_x4(uint32_t* r, uint32_t addr) {
    asm volatile("ldmatrix.sync.aligned.m8n8.x4.shared.b16 {%0,%1,%2,%3}, [%4];"
                 : "=r"(r[0]), "=r"(r[1]), "=r"(r[2]), "=r"(r[3]) : "r"(addr));
}
__device__ __forceinline__ void mma16816(float* c, const uint32_t* a, const uint32_t* b) {
    asm volatile("mma.sync.aligned.m16n8k16.row.col.f32.bf16.bf16.f32 "
                 "{%0,%1,%2,%3}, {%4,%5,%6,%7}, {%8,%9}, {%0,%1,%2,%3};"
                 : "+f"(c[0]), "+f"(c[1]), "+f"(c[2]), "+f"(c[3])
                 : "r"(a[0]), "r"(a[1]), "r"(a[2]), "r"(a[3]), "r"(b[0]), "r"(b[1]));
}

// ---------------- scratch (static __device__, no allocation) ----------------
static __device__ bf16 g_wqkvT_h[3 * DD * DD], g_wqkvT_l[3 * DD * DD];     // [3072,1024]
static __device__ bf16 g_woT_h[DD * DD],       g_woT_l[DD * DD];           // [1024,1024]
static __device__ bf16 g_fw1T_h[FFD * DD],     g_fw1T_l[FFD * DD];         // [4096,1024]
static __device__ bf16 g_fw2T_h[DD * FFD],     g_fw2T_l[DD * FFD];         // [1024,4096]
static __device__ bf16 g_nx_h[ROWS * DD],      g_nx_l[ROWS * DD];
static __device__ bf16 g_qkv_h[ROWS * 3 * DD], g_qkv_l[ROWS * 3 * DD];
static __device__ bf16 g_vt_h[(size_t)BBATCH * HH * PP * TT], g_vt_l[(size_t)BBATCH * HH * PP * TT];
static __device__ bf16 g_nv_h[ROWS * DD],      g_nv_l[ROWS * DD];
static __device__ bf16 g_pre_h[ROWS * DD],     g_pre_l[ROWS * DD];
static __device__ bf16 g_hid_h[(size_t)ROWS * FFD], g_hid_l[(size_t)ROWS * FFD];
static __device__ float g_ss [ROWS * DD];
static __device__ float g_pre[ROWS * DD];

// ---------------- transpose + split: fp32 in [R,C] -> bf16 hi/lo [C,R] ----------------
__global__ void transpose_split(const float* __restrict__ in,
                                bf16* __restrict__ ohi, bf16* __restrict__ olo,
                                int ldin, int ldout, long long sIn, long long sOut) {
    __shared__ float t[32][33];
    const float* ip = in + (long long)blockIdx.z * sIn;
    long long ob = (long long)blockIdx.z * sOut;
    int r0 = blockIdx.y * 32, c0 = blockIdx.x * 32;
    int tx = threadIdx.x, ty = threadIdx.y;
#pragma unroll
    for (int j = 0; j < 32; j += 8)
        t[ty + j][tx] = ip[(long long)(r0 + ty + j) * ldin + c0 + tx];
    __syncthreads();
#pragma unroll
    for (int j = 0; j < 32; j += 8) {
        float v = t[tx][ty + j];
        bf16 h = __float2bfloat16(v);
        long long o = ob + (long long)(c0 + ty + j) * ldout + r0 + tx;
        ohi[o] = h;
        olo[o] = __float2bfloat16(v - __bfloat162float(h));
    }
}

// ---------------- V^T extraction (bf16 -> bf16 transpose per head) ----------------
__global__ void vt_kernel(const bf16* __restrict__ qhi, const bf16* __restrict__ qlo,
                          bf16* __restrict__ vhi, bf16* __restrict__ vlo) {
    __shared__ bf16 th[32][33], tl[32][33];
    int z = blockIdx.z, bb = z >> 4, hh = z & 15;
    const long long ib = (long long)bb * TT * (3 * DD) + 2 * DD + hh * PP;
    const long long ob = (long long)z * PP * TT;
    int t0 = blockIdx.y * 32, p0 = blockIdx.x * 32;
    int tx = threadIdx.x, ty = threadIdx.y;
#pragma unroll
    for (int j = 0; j < 32; j += 8) {
        long long g = ib + (long long)(t0 + ty + j) * (3 * DD) + p0 + tx;
        th[ty + j][tx] = qhi[g];
        tl[ty + j][tx] = qlo[g];
    }
    __syncthreads();
#pragma unroll
    for (int j = 0; j < 32; j += 8) {
        long long o = ob + (long long)(p0 + ty + j) * TT + t0 + tx;
        vhi[o] = th[tx][ty + j];
        vlo[o] = tl[tx][ty + j];
    }
}

// ---------------- layernorm (+opt residual), float4 path ----------------
__global__ void ln_split_kernel(const float* __restrict__ x,
                                const float* __restrict__ gamma,
                                const float* __restrict__ beta,
                                const float* __restrict__ residual,
                                float* __restrict__ outf,
                                bf16* __restrict__ ohi, bf16* __restrict__ olo) {
    int row = blockIdx.x;
    int tid = threadIdx.x;               // 256 threads, 4 contiguous elems each
    long long rb = (long long)row * DD;
    float4 v = *(const float4*)(x + rb + tid * 4);
    float s  = v.x + v.y + v.z + v.w;
    float sq = v.x * v.x + v.y * v.y + v.z * v.z + v.w * v.w;
    __shared__ float red[2][32];
    for (int o = 16; o > 0; o >>= 1) {
        s  += __shfl_xor_sync(0xffffffff, s, o);
        sq += __shfl_xor_sync(0xffffffff, sq, o);
    }
    int wid = tid >> 5, lid = tid & 31;
    if (lid == 0) { red[0][wid] = s; red[1][wid] = sq; }
    __syncthreads();
    if (wid == 0) {
        s = red[0][lid & 7]; sq = red[1][lid & 7];
        for (int o = 4; o > 0; o >>= 1) {
            s  += __shfl_xor_sync(0xffffffff, s, o);
            sq += __shfl_xor_sync(0xffffffff, sq, o);
        }
        if (lid == 0) { red[0][0] = s; red[1][0] = sq; }
    }
    __syncthreads();
    float mean = red[0][0] * (1.0f / DD);
    float var  = red[1][0] * (1.0f / DD) - mean * mean;
    float rstd = rsqrtf(var + 1e-5f);
    float4 gm = *(const float4*)(gamma + tid * 4);
    float4 bt = *(const float4*)(beta  + tid * 4);
    float o0 = (v.x - mean) * rstd * gm.x + bt.x;
    float o1 = (v.y - mean) * rstd * gm.y + bt.y;
    float o2 = (v.z - mean) * rstd * gm.z + bt.z;
    float o3 = (v.w - mean) * rstd * gm.w + bt.w;
    if (residual) {
        float4 rr = *(const float4*)(residual + rb + tid * 4);
        o0 += rr.x; o1 += rr.y; o2 += rr.z; o3 += rr.w;
    }
    if (outf) {
        float4 ov = make_float4(o0, o1, o2, o3);
        *(float4*)(outf + rb + tid * 4) = ov;
    }
    __nv_bfloat162 h01 = __floats2bfloat162_rn(o0, o1);
    __nv_bfloat162 h23 = __floats2bfloat162_rn(o2, o3);
    float2 f01 = __bfloat1622float2(h01);
    float2 f23 = __bfloat1622float2(h23);
    __nv_bfloat162 l01 = __floats2bfloat162_rn(o0 - f01.x, o1 - f01.y);
    __nv_bfloat162 l23 = __floats2bfloat162_rn(o2 - f23.x, o3 - f23.y);
    uint2 hv, lv;
    hv.x = *(uint32_t*)&h01; hv.y = *(uint32_t*)&h23;
    lv.x = *(uint32_t*)&l01; lv.y = *(uint32_t*)&l23;
    *(uint2*)(ohi + rb + tid * 4) = hv;
    *(uint2*)(olo + rb + tid * 4) = lv;
}

// ---------------- softmax over last dim, fp32 in-place only ----------------
__global__ void softmax_kernel(float* __restrict__ a) {
    long long row = blockIdx.x;
    float4* r4 = (float4*)(a + row * (long long)TT);
    int tid = threadIdx.x;               // 256 threads, 2 float4 each
    float4 va = r4[tid], vb = r4[tid + 256];
    float v[8] = {va.x, va.y, va.z, va.w, vb.x, vb.y, vb.z, vb.w};
    float mx = -1e30f;
#pragma unroll
    for (int i = 0; i < 8; i++) mx = fmaxf(mx, v[i]);
    __shared__ float red[32];
    for (int o = 16; o > 0; o >>= 1) mx = fmaxf(mx, __shfl_xor_sync(0xffffffff, mx, o));
    int wid = tid >> 5, lid = tid & 31;
    if (lid == 0) red[wid] = mx;
    __syncthreads();
    if (wid == 0) {
        mx = red[lid & 7];
        for (int o = 4; o > 0; o >>= 1) mx = fmaxf(mx, __shfl_xor_sync(0xffffffff, mx, o));
        if (lid == 0) red[0] = mx;
    }
    __syncthreads();
    mx = red[0];
    float s = 0.f;
#pragma unroll
    for (int i = 0; i < 8; i++) { v[i] = __expf(v[i] - mx); s += v[i]; }
    __syncthreads();
    for (int o = 16; o > 0; o >>= 1) s += __shfl_xor_sync(0xffffffff, s, o);
    if (lid == 0) red[wid] = s;
    __syncthreads();
    if (wid == 0) {
        s = red[lid & 7];
        for (int o = 4; o > 0; o >>= 1) s += __shfl_xor_sync(0xffffffff, s, o);
        if (lid == 0) red[0] = s;
    }
    __syncthreads();
    float inv = 1.0f / red[0];
    r4[tid]       = make_float4(v[0] * inv, v[1] * inv, v[2] * inv, v[3] * inv);
    r4[tid + 256] = make_float4(v[4] * inv, v[5] * inv, v[6] * inv, v[7] * inv);
}

// =====================================================================
// Generic split-bf16 GEMM on mma.sync.  C = alpha * A@B^T.
// A [M,K] hi/lo, B [N,K] hi/lo, K-major bf16.
// Passes: Ahi*Bhi + Alo*Bhi + Ahi*Blo, fp32 accum.
// 128 threads (4 warps, 2x2), warp tile 64x64 (MT=4, NT=8):
// 16 ldsm per 96 mma per ks -> 48 FLOP/smem-byte (1.5x above balance).
// Tile 128 x 128, BK=32 (64B rows, SW64 swizzle), 3-stage cp.async,
// 2 CTAs/SM.  Fused epilogue: bias/GELU/residual; fp32 and/or hi-lo bf16.
// =====================================================================
__global__ __launch_bounds__(128, 2)
void gemm_mma(const bf16* __restrict__ Ahi, const bf16* __restrict__ Alo,
              const bf16* __restrict__ Bhi, const bf16* __restrict__ Blo,
              int K, int lda, int ldb, int ldc,
              float alpha,
              const float* __restrict__ bias,
              const float* __restrict__ residual, int ldres,
              int doGelu,
              float* __restrict__ Cf,
              bf16* __restrict__ Chi, bf16* __restrict__ Clo,
              int hdiv,
              long long sAb, long long sAh,
              long long sBb, long long sBh,
              long long sCb, long long sCh) {
    constexpr int BN = 128;
    constexpr int TILE_A = 128 * 64;
    constexpr int TILE_B = BN * 64;
    constexpr int STAGE  = 2 * TILE_A + 2 * TILE_B;   // 32768
    constexpr int MT = 4, NT = 8;          // warp tile 64x64, warps 2x2

    extern __shared__ char smem[];
    const uint32_t sb = smem_to_u32(smem);

    const int tid  = threadIdx.x;
    const int warp = tid >> 5, lane = tid & 31;
    const int wm = warp >> 1, wn = warp & 1;
    const int rw = wm * 64;
    const int cw = wn * 64;

    int z = blockIdx.z;
    int bbz = z / hdiv, hhz = z % hdiv;
    Ahi += bbz * sAb + hhz * sAh;  Alo += bbz * sAb + hhz * sAh;
    Bhi += bbz * sBb + hhz * sBh;  Blo += bbz * sBb + hhz * sBh;
    const long long coff = bbz * sCb + hhz * sCh;

    const int row0 = blockIdx.y * 128;
    const int col0 = blockIdx.x * BN;

    float acc[MT][NT][4];
#pragma unroll
    for (int i = 0; i < MT; i++)
#pragma unroll
        for (int j = 0; j < NT; j++)
#pragma unroll
            for (int q = 0; q < 4; q++) acc[i][j][q] = 0.f;

    const int nc = K >> 5;

    auto copy_chunk = [&](int k0, int buf) {
        uint32_t ah = sb + buf * STAGE;
        uint32_t bh = ah + 2 * TILE_A;
        uint32_t bl = bh + TILE_B;
#pragma unroll
        for (int l = 0; l < 4; l++) {
            int idx = tid + l * 128;
            int row = idx >> 2, seg = idx & 3;
            long long g = (long long)(row0 + row) * lda + k0 + seg * 8;
            uint32_t sw = SMEM_SWIZZLE_64B((uint32_t)(row * 64 + seg * 16));
            cp16(ah + sw, Ahi + g);
            cp16(ah + TILE_A + sw, Alo + g);
        }
#pragma unroll
        for (int l = 0; l < 4; l++) {
            int idx = tid + l * 128;
            int row = idx >> 2, seg = idx & 3;
            long long g = (long long)(col0 + row) * ldb + k0 + seg * 8;
            uint32_t sw = SMEM_SWIZZLE_64B((uint32_t)(row * 64 + seg * 16));
            cp16(bh + sw, Bhi + g);
            cp16(bl + sw, Blo + g);
        }
    };

    copy_chunk(0, 0);
    CP_COMMIT();
    if (nc > 1) copy_chunk(32, 1);
    CP_COMMIT();

    const int lr = lane & 15;
    const int lk = lane >> 4;
    const int bnrow = (lane & 7) + ((lane >> 4) & 1) * 8;
    const int bkh   = (lane >> 3) & 1;

    for (int c = 0; c < nc; c++) {
        CP_WAIT1();
        __syncthreads();
        if (c + 2 < nc) copy_chunk((c + 2) << 5, (c + 2) % 3);
        CP_COMMIT();

        uint32_t abase = sb + (c % 3) * STAGE;
        uint32_t bbase = abase + 2 * TILE_A;
#pragma unroll
        for (int ks = 0; ks < 2; ks++) {
            uint32_t afh[MT][4], afl[MT][4];
#pragma unroll
            for (int mt = 0; mt < MT; mt++) {
                uint32_t off = SMEM_SWIZZLE_64B((uint32_t)((rw + mt * 16 + lr) * 64 + ks * 32 + lk * 16));
                ldsm_x4(afh[mt], abase + off);
                ldsm_x4(afl[mt], abase + TILE_A + off);
            }
            uint32_t bfh[NT][2], bfl[NT][2];
#pragma unroll
            for (int g = 0; g < NT / 2; g++) {
                uint32_t off = SMEM_SWIZZLE_64B((uint32_t)((cw + g * 16 + bnrow) * 64 + ks * 32 + bkh * 16));
                uint32_t r4[4];
                ldsm_x4(r4, bbase + off);
                bfh[2 * g][0] = r4[0]; bfh[2 * g][1] = r4[1];
                bfh[2 * g + 1][0] = r4[2]; bfh[2 * g + 1][1] = r4[3];
                ldsm_x4(r4, bbase + TILE_B + off);
                bfl[2 * g][0] = r4[0]; bfl[2 * g][1] = r4[1];
                bfl[2 * g + 1][0] = r4[2]; bfl[2 * g + 1][1] = r4[3];
            }
#pragma unroll
            for (int mt = 0; mt < MT; mt++)
#pragma unroll
                for (int nt = 0; nt < NT; nt++) {
                    mma16816(acc[mt][nt], afh[mt], bfh[nt]);
                    mma16816(acc[mt][nt], afl[mt], bfh[nt]);
                    mma16816(acc[mt][nt], afh[mt], bfl[nt]);
                }
        }
    }
    __syncthreads();

    // ---- epilogue ----
    constexpr int SP = BN + 4;
    float* stage = (float*)smem;
    {
        int qr = lane >> 2;
        int qc = (lane & 3) * 2;
#pragma unroll
        for (int mt = 0; mt < MT; mt++) {
            int r1 = rw + mt * 16 + qr;
            int r2 = r1 + 8;
#pragma unroll
            for (int nt = 0; nt < NT; nt++) {
                int cc = cw + nt * 8 + qc;
                stage[r1 * SP + cc]     = acc[mt][nt][0];
                stage[r1 * SP + cc + 1] = acc[mt][nt][1];
                stage[r2 * SP + cc]     = acc[mt][nt][2];
                stage[r2 * SP + cc + 1] = acc[mt][nt][3];
            }
        }
    }
    __syncthreads();
#pragma unroll
    for (int l = 0; l < 32; l++) {
        int idx = tid + l * 128;
        int r2 = idx >> 5;
        int c4 = (idx & 31) * 4;
        int grow = row0 + r2;
        int gcol = col0 + c4;
        float4 v = *(float4*)&stage[r2 * SP + c4];
        float* vp = (float*)&v;
#pragma unroll
        for (int j = 0; j < 4; j++) {
            float x = vp[j] * alpha;
            if (bias) x += bias[gcol + j];
            if (doGelu) x = 0.5f * x * (1.0f + erff(x * 0.70710678118654752f));
            if (residual) x += residual[(long long)grow * ldres + gcol + j];
            vp[j] = x;
        }
        long long o = coff + (long long)grow * ldc + gcol;
        if (Cf) *(float4*)&Cf[o] = v;
        if (Chi) {
            __nv_bfloat162 h01 = __floats2bfloat162_rn(vp[0], vp[1]);
            __nv_bfloat162 h23 = __floats2bfloat162_rn(vp[2], vp[3]);
            float2 f01 = __bfloat1622float2(h01);
            float2 f23 = __bfloat1622float2(h23);
            __nv_bfloat162 l01 = __floats2bfloat162_rn(vp[0] - f01.x, vp[1] - f01.y);
            __nv_bfloat162 l23 = __floats2bfloat162_rn(vp[2] - f23.x, vp[3] - f23.y);
            uint2 hv, lv;
            hv.x = *(uint32_t*)&h01; hv.y = *(uint32_t*)&h23;
            lv.x = *(uint32_t*)&l01; lv.y = *(uint32_t*)&l23;
            *(uint2*)&Chi[o] = hv;
            *(uint2*)&Clo[o] = lv;
        }
    }
}

// =====================================================================
// AV GEMM: A = attn fp32 [T,T] row-major, split to bf16 hi/lo IN-KERNEL.
// B = V^T hi/lo bf16 [P=64, T] K-major.  nv = A @ B^T, full 3-pass.
// Tile 128 x 64, BK=32. A: LDG float4 prefetch -> reg convert -> swizzled
// bf16 tiles (double buffered). B: 3-stage cp.async. 2 CTAs/SM.
// =====================================================================
__global__ __launch_bounds__(256, 2)
void gemm_av(const float* __restrict__ A,
             const bf16* __restrict__ Bhi, const bf16* __restrict__ Blo,
             bf16* __restrict__ Chi, bf16* __restrict__ Clo) {
    constexpr int BN = 64;
    constexpr int TILE_B = BN * 64;            // 4096 B
    constexpr int BSTAGE = 2 * TILE_B;         // 8192
    constexpr int TILE_A = 128 * 64;           // 8192 (bf16 tile bytes)
    constexpr int ABUF   = 2 * TILE_A;         // hi+lo = 16384
    constexpr int A_OFF  = 3 * BSTAGE;         // 24576
    constexpr int MT = 2, NT = 4;              // warps 4x2

    extern __shared__ char smem[];
    const uint32_t sb = smem_to_u32(smem);

    const int tid  = threadIdx.x;
    const int warp = tid >> 5, lane = tid & 31;
    const int wm = warp >> 1, wn = warp & 1;
    const int rw = wm * 32;
    const int cw = wn * 32;

    const int z = blockIdx.z;                  // bh index
    const int bbz = z >> 4, hhz = z & 15;
    A   += (long long)z * TT * TT;
    Bhi += (long long)z * PP * TT;
    Blo += (long long)z * PP * TT;
    const long long coff = (long long)bbz * TT * DD + hhz * PP;

    const int row0 = blockIdx.y * 128;

    float acc[MT][NT][4];
#pragma unroll
    for (int i = 0; i < MT; i++)
#pragma unroll
        for (int j = 0; j < NT; j++)
#pragma unroll
            for (int q = 0; q < 4; q++) acc[i][j][q] = 0.f;

    const int nc = TT >> 5;                    // 64

    float4 ar[4];

    auto loadA = [&](int k0) {
#pragma unroll
        for (int l = 0; l < 4; l++) {
            int idx = tid + l * 256;
            int row = idx >> 3, seg = idx & 7;
            ar[l] = *(const float4*)(A + (long long)(row0 + row) * TT + k0 + seg * 4);
        }
    };
    auto convStoreA = [&](int buf) {
        uint32_t ah = sb + A_OFF + buf * ABUF;
        uint32_t al = ah + TILE_A;
#pragma unroll
        for (int l = 0; l < 4; l++) {
            int idx = tid + l * 256;
            int row = idx >> 3, seg = idx & 7;
            uint32_t sw = SMEM_SWIZZLE_64B((uint32_t)(row * 64 + seg * 8));
            float4 v = ar[l];
            __nv_bfloat162 h01 = __floats2bfloat162_rn(v.x, v.y);
            __nv_bfloat162 h23 = __floats2bfloat162_rn(v.z, v.w);
            float2 f01 = __bfloat1622float2(h01);
            float2 f23 = __bfloat1622float2(h23);
            __nv_bfloat162 l01 = __floats2bfloat162_rn(v.x - f01.x, v.y - f01.y);
            __nv_bfloat162 l23 = __floats2bfloat162_rn(v.z - f23.x, v.w - f23.y);
            uint2 hv, lv;
            hv.x = *(uint32_t*)&h01; hv.y = *(uint32_t*)&h23;
            lv.x = *(uint32_t*)&l01; lv.y = *(uint32_t*)&l23;
            *(uint2*)(smem + (ah - sb) + sw) = hv;
            *(uint2*)(smem + (al - sb) + sw) = lv;
        }
    };
    auto copyB = [&](int k0, int buf) {
        uint32_t bh = sb + buf * BSTAGE;
        uint32_t bl = bh + TILE_B;
        int idx = tid;                          // 256 threads cover 64 rows x 4 segs
        int row = idx >> 2, seg = idx & 3;
        long long g = (long long)row * TT + k0 + seg * 8;
        uint32_t sw = SMEM_SWIZZLE_64B((uint32_t)(row * 64 + seg * 16));
        cp16(bh + sw, Bhi + g);
        cp16(bl + sw, Blo + g);
    };

    // prologue
    loadA(0);
    convStoreA(0);
    loadA(32);
    copyB(0, 0);
    CP_COMMIT();
    copyB(32, 1);
    CP_COMMIT();
    __syncthreads();    // A buf0 visible to all warps

    const int lr = lane & 15;
    const int lk = lane >> 4;
    const int bnrow = (lane & 7) + ((lane >> 4) & 1) * 8;
    const int bkh   = (lane >> 3) & 1;

    for (int c = 0; c < nc; c++) {
        CP_WAIT1();
        __syncthreads();
        if (c + 2 < nc) copyB((c + 2) << 5, (c + 2) % 3);
        CP_COMMIT();
        if (c + 1 < nc) convStoreA((c + 1) & 1);   // regs hold chunk c+1
        if (c + 2 < nc) loadA((c + 2) << 5);

        uint32_t abase = sb + A_OFF + (c & 1) * ABUF;
        uint32_t bbase = sb + (c % 3) * BSTAGE;
#pragma unroll
        for (int ks = 0; ks < 2; ks++) {
            uint32_t afh[MT][4], afl[MT][4];
#pragma unroll
            for (int mt = 0; mt < MT; mt++) {
                uint32_t off = SMEM_SWIZZLE_64B((uint32_t)((rw + mt * 16 + lr) * 64 + ks * 32 + lk * 16));
                ldsm_x4(afh[mt], abase + off);
                ldsm_x4(afl[mt], abase + TILE_A + off);
            }
            uint32_t bfh[NT][2], bfl[NT][2];
#pragma unroll
            for (int g = 0; g < NT / 2; g++) {
                uint32_t off = SMEM_SWIZZLE_64B((uint32_t)((cw + g * 16 + bnrow) * 64 + ks * 32 + bkh * 16));
                uint32_t r4[4];
                ldsm_x4(r4, bbase + off);
                bfh[2 * g][0] = r4[0]; bfh[2 * g][1] = r4[1];
                bfh[2 * g + 1][0] = r4[2]; bfh[2 * g + 1][1] = r4[3];
                ldsm_x4(r4, bbase + TILE_B + off);
                bfl[2 * g][0] = r4[0]; bfl[2 * g][1] = r4[1];
                bfl[2 * g + 1][0] = r4[2]; bfl[2 * g + 1][1] = r4[3];
            }
#pragma unroll
            for (int mt = 0; mt < MT; mt++)
#pragma unroll
                for (int nt = 0; nt < NT; nt++) {
                    mma16816(acc[mt][nt], afh[mt], bfh[nt]);
                    mma16816(acc[mt][nt], afl[mt], bfh[nt]);
                    mma16816(acc[mt][nt], afh[mt], bfl[nt]);
                }
        }
    }
    __syncthreads();

    // ---- epilogue: hi/lo bf16 out ----
    constexpr int SP = BN + 4;
    float* stage = (float*)smem;
    {
        int qr = lane >> 2;
        int qc = (lane & 3) * 2;
#pragma unroll
        for (int mt = 0; mt < MT; mt++) {
            int r1 = rw + mt * 16 + qr;
            int r2 = r1 + 8;
#pragma unroll
            for (int nt = 0; nt < NT; nt++) {
                int cc = cw + nt * 8 + qc;
                stage[r1 * SP + cc]     = acc[mt][nt][0];
                stage[r1 * SP + cc + 1] = acc[mt][nt][1];
                stage[r2 * SP + cc]     = acc[mt][nt][2];
                stage[r2 * SP + cc + 1] = acc[mt][nt][3];
            }
        }
    }
    __syncthreads();
#pragma unroll
    for (int l = 0; l < BN / 8; l++) {
        int idx = tid + l * 256;
        int r2 = idx / (BN / 4);
        int c4 = (idx % (BN / 4)) * 4;
        int grow = row0 + r2;
        float4 v = *(float4*)&stage[r2 * SP + c4];
        long long o = coff + (long long)grow * DD + c4;
        __nv_bfloat162 h01 = __floats2bfloat162_rn(v.x, v.y);
        __nv_bfloat162 h23 = __floats2bfloat162_rn(v.z, v.w);
        float2 f01 = __bfloat1622float2(h01);
        float2 f23 = __bfloat1622float2(h23);
        __nv_bfloat162 l01 = __floats2bfloat162_rn(v.x - f01.x, v.y - f01.y);
        __nv_bfloat162 l23 = __floats2bfloat162_rn(v.z - f23.x, v.w - f23.y);
        uint2 hv, lv;
        hv.x = *(uint32_t*)&h01; hv.y = *(uint32_t*)&h23;
        lv.x = *(uint32_t*)&l01; lv.y = *(uint32_t*)&l23;
        *(uint2*)&Chi[o] = hv;
        *(uint2*)&Clo[o] = lv;
    }
}

// ---------------- host side ----------------
// gemm_mma: 3 stages x 32768 = 98304; epi 128*132*4 = 67584 -> 98304
// gemm_av: 3*8192 + 2*16384 = 57344; epi 128*68*4 = 34816 -> 57344
static const int SMEM_G = 98304;
static const int SMEM_AV = 57344;

extern "C" void kernel_launch(void* const* d_in, const int* in_sizes, int n_in,
                              void* d_out, int out_size) {
    const float* X      = (const float*)d_in[0];
    const float* WQ     = (const float*)d_in[1];
    const float* WK     = (const float*)d_in[2];
    const float* WV     = (const float*)d_in[3];
    const float* WO     = (const float*)d_in[4];
    const float* attn_g = (const float*)d_in[5];
    const float* attn_b = (const float*)d_in[6];
    const float* ff_g   = (const float*)d_in[7];
    const float* ff_b   = (const float*)d_in[8];
    const float* fW1    = (const float*)d_in[9];
    const float* fb1    = (const float*)d_in[10];
    const float* fW2    = (const float*)d_in[11];
    const float* fb2    = (const float*)d_in[12];

    float* out0 = (float*)d_out;                         // [B,T,D]
    float* attn = out0 + (long long)ROWS * DD;           // [B,H,T,T]

    cudaFuncSetAttribute(gemm_mma, cudaFuncAttributeMaxDynamicSharedMemorySize, SMEM_G);
    cudaFuncSetAttribute(gemm_av,  cudaFuncAttributeMaxDynamicSharedMemorySize, SMEM_AV);

    bf16 *wqkvT_h, *wqkvT_l, *woT_h, *woT_l, *fw1T_h, *fw1T_l, *fw2T_h, *fw2T_l;
    bf16 *nx_h, *nx_l, *qkv_h, *qkv_l, *vt_h, *vt_l;
    bf16 *nv_h, *nv_l, *pre_h, *pre_l, *hid_h, *hid_l;
    float *ss, *pre;
    cudaGetSymbolAddress((void**)&wqkvT_h, g_wqkvT_h); cudaGetSymbolAddress((void**)&wqkvT_l, g_wqkvT_l);
    cudaGetSymbolAddress((void**)&woT_h,  g_woT_h);    cudaGetSymbolAddress((void**)&woT_l,  g_woT_l);
    cudaGetSymbolAddress((void**)&fw1T_h, g_fw1T_h);   cudaGetSymbolAddress((void**)&fw1T_l, g_fw1T_l);
    cudaGetSymbolAddress((void**)&fw2T_h, g_fw2T_h);   cudaGetSymbolAddress((void**)&fw2T_l, g_fw2T_l);
    cudaGetSymbolAddress((void**)&nx_h,   g_nx_h);     cudaGetSymbolAddress((void**)&nx_l,   g_nx_l);
    cudaGetSymbolAddress((void**)&qkv_h,  g_qkv_h);    cudaGetSymbolAddress((void**)&qkv_l,  g_qkv_l);
    cudaGetSymbolAddress((void**)&vt_h,   g_vt_h);     cudaGetSymbolAddress((void**)&vt_l,   g_vt_l);
    cudaGetSymbolAddress((void**)&nv_h,   g_nv_h);     cudaGetSymbolAddress((void**)&nv_l,   g_nv_l);
    cudaGetSymbolAddress((void**)&pre_h,  g_pre_h);    cudaGetSymbolAddress((void**)&pre_l,  g_pre_l);
    cudaGetSymbolAddress((void**)&hid_h,  g_hid_h);    cudaGetSymbolAddress((void**)&hid_l,  g_hid_l);
    cudaGetSymbolAddress((void**)&ss,     g_ss);       cudaGetSymbolAddress((void**)&pre,    g_pre);

    dim3 tb32(32, 8);

    // 1. weight transposes + splits
    transpose_split<<<dim3(2, 32, 16), tb32>>>(WQ, wqkvT_h,                wqkvT_l,                64, DD, (long long)DD * PP, (long long)PP * DD);
    transpose_split<<<dim3(2, 32, 16), tb32>>>(WK, wqkvT_h + DD * DD,      wqkvT_l + DD * DD,      64, DD, (long long)DD * PP, (long long)PP * DD);
    transpose_split<<<dim3(2, 32, 16), tb32>>>(WV, wqkvT_h + 2 * DD * DD,  wqkvT_l + 2 * DD * DD,  64, DD, (long long)DD * PP, (long long)PP * DD);
    transpose_split<<<dim3(128, 32, 1), tb32>>>(fW1, fw1T_h, fw1T_l, FFD, DD, 0, 0);
    transpose_split<<<dim3(32, 128, 1), tb32>>>(fW2, fw2T_h, fw2T_l, DD, FFD, 0, 0);
    transpose_split<<<dim3(32, 32, 1),  tb32>>>(WO,  woT_h,  woT_l,  DD, DD, 0, 0);

    // 2. LN1 -> nx hi/lo
    ln_split_kernel<<<ROWS, 256>>>(X, attn_g, attn_b, nullptr, nullptr, nx_h, nx_l);

    // 3. QKV: [8192,1024] x [3072,1024]^T -> qkv hi/lo [8192,3072]
    gemm_mma<<<dim3(24, 64, 1), 128, SMEM_G>>>(
        nx_h, nx_l, wqkvT_h, wqkvT_l, DD, DD, DD, 3 * DD,
        1.f, nullptr, nullptr, 0, 0, nullptr, qkv_h, qkv_l,
        1, 0, 0, 0, 0, 0, 0);

    // 4. V^T per head
    vt_kernel<<<dim3(2, 64, 64), tb32>>>(qkv_h, qkv_l, vt_h, vt_l);

    // 5. scores (faithful index swap): rows = K-tokens, cols = Q-tokens
    gemm_mma<<<dim3(16, 16, 64), 128, SMEM_G>>>(
        qkv_h + DD, qkv_l + DD, qkv_h, qkv_l, PP, 3 * DD, 3 * DD, TT,
        0.125f, nullptr, nullptr, 0, 0, attn, nullptr, nullptr,
        16,
        (long long)TT * 3 * DD, PP,
        (long long)TT * 3 * DD, PP,
        16LL * TT * TT, (long long)TT * TT);

    // 6. softmax, fp32 in-place only
    softmax_kernel<<<BBATCH * HH * TT, 256>>>(attn);

    // 7. AV: attn fp32 (split in-kernel, 3-pass) x V^T hi/lo -> nv hi/lo
    gemm_av<<<dim3(1, 16, 64), 256, SMEM_AV>>>(attn, vt_h, vt_l, nv_h, nv_l);

    // 8. WO: [8192,1024] x [1024,1024]^T -> ss fp32
    gemm_mma<<<dim3(8, 64, 1), 128, SMEM_G>>>(
        nv_h, nv_l, woT_h, woT_l, DD, DD, DD, DD,
        1.f, nullptr, nullptr, 0, 0, ss, nullptr, nullptr,
        1, 0, 0, 0, 0, 0, 0);

    // 9. pre_ff = X + LN(ss): fp32 + hi/lo
    ln_split_kernel<<<ROWS, 256>>>(ss, ff_g, ff_b, X, pre, pre_h, pre_l);

    // 10. FF1 + bias + gelu -> hid hi/lo
    gemm_mma<<<dim3(32, 64, 1), 128, SMEM_G>>>(
        pre_h, pre_l, fw1T_h, fw1T_l, DD, DD, DD, FFD,
        1.f, fb1, nullptr, 0, 1, nullptr, hid_h, hid_l,
        1, 0, 0, 0, 0, 0, 0);

    // 11. FF2 + bias + residual(pre) -> out0 fp32
    gemm_mma<<<dim3(8, 64, 1), 128, SMEM_G>>>(
        hid_h, hid_l, fw2T_h, fw2T_l, FFD, FFD, FFD, DD,
        1.f, fb2, pre, DD, 0, out0, nullptr, nullptr,
        1, 0, 0, 0, 0, 0, 0);
}

// round 12
// speedup vs baseline: 1.0681x; 1.0681x over previous
#include <cuda_runtime.h>
#include <cuda_bf16.h>
#include <cstdint>
#include <math.h>

// ---------------- problem constants ----------------
#define BBATCH 4
#define TT 2048
#define DD 1024
#define HH 16
#define PP 64
#define FFD 4096
#define ROWS (BBATCH*TT)          // 8192

typedef __nv_bfloat16 bf16;

#define SMEM_SWIZZLE_64B(off)  ((off) ^ (((off) >> 3) & 0x30))

__device__ __forceinline__ uint32_t smem_to_u32(const void* p) {
    uint32_t a;
    asm("{ .reg .u64 t; cvta.to.shared.u64 t, %1; cvt.u32.u64 %0, t; }" : "=r"(a) : "l"(p));
    return a;
}
__device__ __forceinline__ void cp16(uint32_t s, const void* g) {
    asm volatile("cp.async.cg.shared.global [%0], [%1], 16;" :: "r"(s), "l"(g));
}
#define CP_COMMIT() asm volatile("cp.async.commit_group;" ::: "memory")
#define CP_WAIT1()  asm volatile("cp.async.wait_group 1;" ::: "memory")

__device__ __forceinline__ void ldsm_x4(uint32_t* r, uint32_t addr) {
    asm volatile("ldmatrix.sync.aligned.m8n8.x4.shared.b16 {%0,%1,%2,%3}, [%4];"
                 : "=r"(r[0]), "=r"(r[1]), "=r"(r[2]), "=r"(r[3]) : "r"(addr));
}
__device__ __forceinline__ void mma16816(float* c, const uint32_t* a, const uint32_t* b) {
    asm volatile("mma.sync.aligned.m16n8k16.row.col.f32.bf16.bf16.f32 "
                 "{%0,%1,%2,%3}, {%4,%5,%6,%7}, {%8,%9}, {%0,%1,%2,%3};"
                 : "+f"(c[0]), "+f"(c[1]), "+f"(c[2]), "+f"(c[3])
                 : "r"(a[0]), "r"(a[1]), "r"(a[2]), "r"(a[3]), "r"(b[0]), "r"(b[1]));
}

// ---------------- scratch (static __device__, no allocation) ----------------
static __device__ bf16 g_wqkvT_h[3 * DD * DD], g_wqkvT_l[3 * DD * DD];     // [3072,1024]
static __device__ bf16 g_woT_h[DD * DD],       g_woT_l[DD * DD];           // [1024,1024]
static __device__ bf16 g_fw1T_h[FFD * DD],     g_fw1T_l[FFD * DD];         // [4096,1024]
static __device__ bf16 g_fw2T_h[DD * FFD],     g_fw2T_l[DD * FFD];         // [1024,4096]
static __device__ bf16 g_nx_h[ROWS * DD],      g_nx_l[ROWS * DD];
static __device__ bf16 g_qkv_h[ROWS * 3 * DD], g_qkv_l[ROWS * 3 * DD];
static __device__ bf16 g_vt_h[(size_t)BBATCH * HH * PP * TT], g_vt_l[(size_t)BBATCH * HH * PP * TT];
static __device__ bf16 g_nv_h[ROWS * DD],      g_nv_l[ROWS * DD];
static __device__ bf16 g_pre_h[ROWS * DD],     g_pre_l[ROWS * DD];
static __device__ bf16 g_hid_h[(size_t)ROWS * FFD], g_hid_l[(size_t)ROWS * FFD];
static __device__ float g_ss [ROWS * DD];
static __device__ float g_pre[ROWS * DD];

// ---------------- transpose + split: fp32 in [R,C] -> bf16 hi/lo [C,R] ----------------
__global__ void transpose_split(const float* __restrict__ in,
                                bf16* __restrict__ ohi, bf16* __restrict__ olo,
                                int ldin, int ldout, long long sIn, long long sOut) {
    __shared__ float t[32][33];
    const float* ip = in + (long long)blockIdx.z * sIn;
    long long ob = (long long)blockIdx.z * sOut;
    int r0 = blockIdx.y * 32, c0 = blockIdx.x * 32;
    int tx = threadIdx.x, ty = threadIdx.y;
#pragma unroll
    for (int j = 0; j < 32; j += 8)
        t[ty + j][tx] = ip[(long long)(r0 + ty + j) * ldin + c0 + tx];
    __syncthreads();
#pragma unroll
    for (int j = 0; j < 32; j += 8) {
        float v = t[tx][ty + j];
        bf16 h = __float2bfloat16(v);
        long long o = ob + (long long)(c0 + ty + j) * ldout + r0 + tx;
        ohi[o] = h;
        olo[o] = __float2bfloat16(v - __bfloat162float(h));
    }
}

// ---------------- V^T extraction (bf16 -> bf16 transpose per head) ----------------
__global__ void vt_kernel(const bf16* __restrict__ qhi, const bf16* __restrict__ qlo,
                          bf16* __restrict__ vhi, bf16* __restrict__ vlo) {
    __shared__ bf16 th[32][33], tl[32][33];
    int z = blockIdx.z, bb = z >> 4, hh = z & 15;
    const long long ib = (long long)bb * TT * (3 * DD) + 2 * DD + hh * PP;
    const long long ob = (long long)z * PP * TT;
    int t0 = blockIdx.y * 32, p0 = blockIdx.x * 32;
    int tx = threadIdx.x, ty = threadIdx.y;
#pragma unroll
    for (int j = 0; j < 32; j += 8) {
        long long g = ib + (long long)(t0 + ty + j) * (3 * DD) + p0 + tx;
        th[ty + j][tx] = qhi[g];
        tl[ty + j][tx] = qlo[g];
    }
    __syncthreads();
#pragma unroll
    for (int j = 0; j < 32; j += 8) {
        long long o = ob + (long long)(p0 + ty + j) * TT + t0 + tx;
        vhi[o] = th[tx][ty + j];
        vlo[o] = tl[tx][ty + j];
    }
}

// ---------------- layernorm (+opt residual), float4 path ----------------
__global__ void ln_split_kernel(const float* __restrict__ x,
                                const float* __restrict__ gamma,
                                const float* __restrict__ beta,
                                const float* __restrict__ residual,
                                float* __restrict__ outf,
                                bf16* __restrict__ ohi, bf16* __restrict__ olo) {
    int row = blockIdx.x;
    int tid = threadIdx.x;               // 256 threads, 4 contiguous elems each
    long long rb = (long long)row * DD;
    float4 v = *(const float4*)(x + rb + tid * 4);
    float s  = v.x + v.y + v.z + v.w;
    float sq = v.x * v.x + v.y * v.y + v.z * v.z + v.w * v.w;
    __shared__ float red[2][32];
    for (int o = 16; o > 0; o >>= 1) {
        s  += __shfl_xor_sync(0xffffffff, s, o);
        sq += __shfl_xor_sync(0xffffffff, sq, o);
    }
    int wid = tid >> 5, lid = tid & 31;
    if (lid == 0) { red[0][wid] = s; red[1][wid] = sq; }
    __syncthreads();
    if (wid == 0) {
        s = red[0][lid & 7]; sq = red[1][lid & 7];
        for (int o = 4; o > 0; o >>= 1) {
            s  += __shfl_xor_sync(0xffffffff, s, o);
            sq += __shfl_xor_sync(0xffffffff, sq, o);
        }
        if (lid == 0) { red[0][0] = s; red[1][0] = sq; }
    }
    __syncthreads();
    float mean = red[0][0] * (1.0f / DD);
    float var  = red[1][0] * (1.0f / DD) - mean * mean;
    float rstd = rsqrtf(var + 1e-5f);
    float4 gm = *(const float4*)(gamma + tid * 4);
    float4 bt = *(const float4*)(beta  + tid * 4);
    float o0 = (v.x - mean) * rstd * gm.x + bt.x;
    float o1 = (v.y - mean) * rstd * gm.y + bt.y;
    float o2 = (v.z - mean) * rstd * gm.z + bt.z;
    float o3 = (v.w - mean) * rstd * gm.w + bt.w;
    if (residual) {
        float4 rr = *(const float4*)(residual + rb + tid * 4);
        o0 += rr.x; o1 += rr.y; o2 += rr.z; o3 += rr.w;
    }
    if (outf) {
        float4 ov = make_float4(o0, o1, o2, o3);
        *(float4*)(outf + rb + tid * 4) = ov;
    }
    __nv_bfloat162 h01 = __floats2bfloat162_rn(o0, o1);
    __nv_bfloat162 h23 = __floats2bfloat162_rn(o2, o3);
    float2 f01 = __bfloat1622float2(h01);
    float2 f23 = __bfloat1622float2(h23);
    __nv_bfloat162 l01 = __floats2bfloat162_rn(o0 - f01.x, o1 - f01.y);
    __nv_bfloat162 l23 = __floats2bfloat162_rn(o2 - f23.x, o3 - f23.y);
    uint2 hv, lv;
    hv.x = *(uint32_t*)&h01; hv.y = *(uint32_t*)&h23;
    lv.x = *(uint32_t*)&l01; lv.y = *(uint32_t*)&l23;
    *(uint2*)(ohi + rb + tid * 4) = hv;
    *(uint2*)(olo + rb + tid * 4) = lv;
}

// ---------------- softmax: one WARP per row of 2048, fp32 in-place ----------------
// 8 warps/block. Each lane holds 64 elems (16 float4, MLP=16).
// Pure shfl reductions — no block barriers.
__global__ __launch_bounds__(256)
void softmax_kernel(float* __restrict__ a) {
    int warp = threadIdx.x >> 5, lane = threadIdx.x & 31;
    long long row = (long long)blockIdx.x * 8 + warp;
    float4* r4 = (float4*)(a + row * (long long)TT);
    // lane l owns float4 indices l, l+32, l+64, ..., l+480 (16 of them)
    float4 v[16];
#pragma unroll
    for (int i = 0; i < 16; i++) v[i] = r4[lane + i * 32];
    float mx = -1e30f;
#pragma unroll
    for (int i = 0; i < 16; i++) {
        mx = fmaxf(mx, fmaxf(fmaxf(v[i].x, v[i].y), fmaxf(v[i].z, v[i].w)));
    }
#pragma unroll
    for (int o = 16; o > 0; o >>= 1) mx = fmaxf(mx, __shfl_xor_sync(0xffffffff, mx, o));
    float s = 0.f;
#pragma unroll
    for (int i = 0; i < 16; i++) {
        v[i].x = __expf(v[i].x - mx); s += v[i].x;
        v[i].y = __expf(v[i].y - mx); s += v[i].y;
        v[i].z = __expf(v[i].z - mx); s += v[i].z;
        v[i].w = __expf(v[i].w - mx); s += v[i].w;
    }
#pragma unroll
    for (int o = 16; o > 0; o >>= 1) s += __shfl_xor_sync(0xffffffff, s, o);
    float inv = 1.0f / s;
#pragma unroll
    for (int i = 0; i < 16; i++) {
        v[i].x *= inv; v[i].y *= inv; v[i].z *= inv; v[i].w *= inv;
        r4[lane + i * 32] = v[i];
    }
}

// =====================================================================
// Generic split-bf16 GEMM on mma.sync (R10 config).  C = alpha * A@B^T.
// A [M,K] hi/lo, B [N,K] hi/lo, K-major bf16.
// Passes: Ahi*Bhi + Alo*Bhi + Ahi*Blo, fp32 accum.
// 256 threads, tile 128 x 128, BK=32 (64B rows, SW64 swizzle),
// 3-stage cp.async pipeline; 2 CTAs/SM.
// =====================================================================
__global__ __launch_bounds__(256, 2)
void gemm_mma(const bf16* __restrict__ Ahi, const bf16* __restrict__ Alo,
              const bf16* __restrict__ Bhi, const bf16* __restrict__ Blo,
              int K, int lda, int ldb, int ldc,
              float alpha,
              const float* __restrict__ bias,
              const float* __restrict__ residual, int ldres,
              int doGelu,
              float* __restrict__ Cf,
              bf16* __restrict__ Chi, bf16* __restrict__ Clo,
              int hdiv,
              long long sAb, long long sAh,
              long long sBb, long long sBh,
              long long sCb, long long sCh) {
    constexpr int BN = 128;
    constexpr int TILE_A = 128 * 64;
    constexpr int TILE_B = BN * 64;
    constexpr int STAGE  = 2 * TILE_A + 2 * TILE_B;
    constexpr int MT = 4, NT = 4;          // warps 2x4, warp tile 64x32

    extern __shared__ char smem[];
    const uint32_t sb = smem_to_u32(smem);

    const int tid  = threadIdx.x;
    const int warp = tid >> 5, lane = tid & 31;
    const int wm = warp >> 2, wn = warp & 3;
    const int rw = wm * 64;
    const int cw = wn * 32;

    int z = blockIdx.z;
    int bbz = z / hdiv, hhz = z % hdiv;
    Ahi += bbz * sAb + hhz * sAh;  Alo += bbz * sAb + hhz * sAh;
    Bhi += bbz * sBb + hhz * sBh;  Blo += bbz * sBb + hhz * sBh;
    const long long coff = bbz * sCb + hhz * sCh;

    const int row0 = blockIdx.y * 128;
    const int col0 = blockIdx.x * BN;

    float acc[MT][NT][4];
#pragma unroll
    for (int i = 0; i < MT; i++)
#pragma unroll
        for (int j = 0; j < NT; j++)
#pragma unroll
            for (int q = 0; q < 4; q++) acc[i][j][q] = 0.f;

    const int nc = K >> 5;

    auto copy_chunk = [&](int k0, int buf) {
        uint32_t ah = sb + buf * STAGE;
        uint32_t bh = ah + 2 * TILE_A;
        uint32_t bl = bh + TILE_B;
#pragma unroll
        for (int l = 0; l < 2; l++) {
            int idx = tid + l * 256;
            int row = idx >> 2, seg = idx & 3;
            long long g = (long long)(row0 + row) * lda + k0 + seg * 8;
            uint32_t sw = SMEM_SWIZZLE_64B((uint32_t)(row * 64 + seg * 16));
            cp16(ah + sw, Ahi + g);
            cp16(ah + TILE_A + sw, Alo + g);
        }
#pragma unroll
        for (int l = 0; l < 2; l++) {
            int idx = tid + l * 256;
            int row = idx >> 2, seg = idx & 3;
            long long g = (long long)(col0 + row) * ldb + k0 + seg * 8;
            uint32_t sw = SMEM_SWIZZLE_64B((uint32_t)(row * 64 + seg * 16));
            cp16(bh + sw, Bhi + g);
            cp16(bl + sw, Blo + g);
        }
    };

    copy_chunk(0, 0);
    CP_COMMIT();
    if (nc > 1) copy_chunk(32, 1);
    CP_COMMIT();

    const int lr = lane & 15;
    const int lk = lane >> 4;
    const int bnrow = (lane & 7) + ((lane >> 4) & 1) * 8;
    const int bkh   = (lane >> 3) & 1;

    for (int c = 0; c < nc; c++) {
        CP_WAIT1();
        __syncthreads();
        if (c + 2 < nc) copy_chunk((c + 2) << 5, (c + 2) % 3);
        CP_COMMIT();

        uint32_t abase = sb + (c % 3) * STAGE;
        uint32_t bbase = abase + 2 * TILE_A;
#pragma unroll
        for (int ks = 0; ks < 2; ks++) {
            uint32_t afh[MT][4], afl[MT][4];
#pragma unroll
            for (int mt = 0; mt < MT; mt++) {
                uint32_t off = SMEM_SWIZZLE_64B((uint32_t)((rw + mt * 16 + lr) * 64 + ks * 32 + lk * 16));
                ldsm_x4(afh[mt], abase + off);
                ldsm_x4(afl[mt], abase + TILE_A + off);
            }
            uint32_t bfh[NT][2], bfl[NT][2];
#pragma unroll
            for (int g = 0; g < NT / 2; g++) {
                uint32_t off = SMEM_SWIZZLE_64B((uint32_t)((cw + g * 16 + bnrow) * 64 + ks * 32 + bkh * 16));
                uint32_t r4[4];
                ldsm_x4(r4, bbase + off);
                bfh[2 * g][0] = r4[0]; bfh[2 * g][1] = r4[1];
                bfh[2 * g + 1][0] = r4[2]; bfh[2 * g + 1][1] = r4[3];
                ldsm_x4(r4, bbase + TILE_B + off);
                bfl[2 * g][0] = r4[0]; bfl[2 * g][1] = r4[1];
                bfl[2 * g + 1][0] = r4[2]; bfl[2 * g + 1][1] = r4[3];
            }
#pragma unroll
            for (int mt = 0; mt < MT; mt++)
#pragma unroll
                for (int nt = 0; nt < NT; nt++) {
                    mma16816(acc[mt][nt], afh[mt], bfh[nt]);
                    mma16816(acc[mt][nt], afl[mt], bfh[nt]);
                    mma16816(acc[mt][nt], afh[mt], bfl[nt]);
                }
        }
    }
    __syncthreads();

    // ---- epilogue ----
    constexpr int SP = BN + 4;
    float* stage = (float*)smem;
    {
        int qr = lane >> 2;
        int qc = (lane & 3) * 2;
#pragma unroll
        for (int mt = 0; mt < MT; mt++) {
            int r1 = rw + mt * 16 + qr;
            int r2 = r1 + 8;
#pragma unroll
            for (int nt = 0; nt < NT; nt++) {
                int cc = cw + nt * 8 + qc;
                stage[r1 * SP + cc]     = acc[mt][nt][0];
                stage[r1 * SP + cc + 1] = acc[mt][nt][1];
                stage[r2 * SP + cc]     = acc[mt][nt][2];
                stage[r2 * SP + cc + 1] = acc[mt][nt][3];
            }
        }
    }
    __syncthreads();
#pragma unroll
    for (int l = 0; l < BN / 8; l++) {
        int idx = tid + l * 256;
        int r2 = idx / (BN / 4);
        int c4 = (idx % (BN / 4)) * 4;
        int grow = row0 + r2;
        int gcol = col0 + c4;
        float4 v = *(float4*)&stage[r2 * SP + c4];
        float* vp = (float*)&v;
#pragma unroll
        for (int j = 0; j < 4; j++) {
            float x = vp[j] * alpha;
            if (bias) x += bias[gcol + j];
            if (doGelu) x = 0.5f * x * (1.0f + erff(x * 0.70710678118654752f));
            if (residual) x += residual[(long long)grow * ldres + gcol + j];
            vp[j] = x;
        }
        long long o = coff + (long long)grow * ldc + gcol;
        if (Cf) *(float4*)&Cf[o] = v;
        if (Chi) {
            __nv_bfloat162 h01 = __floats2bfloat162_rn(vp[0], vp[1]);
            __nv_bfloat162 h23 = __floats2bfloat162_rn(vp[2], vp[3]);
            float2 f01 = __bfloat1622float2(h01);
            float2 f23 = __bfloat1622float2(h23);
            __nv_bfloat162 l01 = __floats2bfloat162_rn(vp[0] - f01.x, vp[1] - f01.y);
            __nv_bfloat162 l23 = __floats2bfloat162_rn(vp[2] - f23.x, vp[3] - f23.y);
            uint2 hv, lv;
            hv.x = *(uint32_t*)&h01; hv.y = *(uint32_t*)&h23;
            lv.x = *(uint32_t*)&l01; lv.y = *(uint32_t*)&l23;
            *(uint2*)&Chi[o] = hv;
            *(uint2*)&Clo[o] = lv;
        }
    }
}

// =====================================================================
// AV GEMM: A = attn fp32 [T,T] row-major, split to bf16 hi/lo IN-KERNEL.
// B = V^T hi/lo bf16 [P=64, T] K-major.  nv = A @ B^T, full 3-pass.
// Tile 128 x 64, BK=32. A: LDG float4 prefetch -> reg convert -> swizzled
// bf16 tiles (double buffered). B: 3-stage cp.async. 2 CTAs/SM.
// =====================================================================
__global__ __launch_bounds__(256, 2)
void gemm_av(const float* __restrict__ A,
             const bf16* __restrict__ Bhi, const bf16* __restrict__ Blo,
             bf16* __restrict__ Chi, bf16* __restrict__ Clo) {
    constexpr int BN = 64;
    constexpr int TILE_B = BN * 64;            // 4096 B
    constexpr int BSTAGE = 2 * TILE_B;         // 8192
    constexpr int TILE_A = 128 * 64;           // 8192 (bf16 tile bytes)
    constexpr int ABUF   = 2 * TILE_A;         // hi+lo = 16384
    constexpr int A_OFF  = 3 * BSTAGE;         // 24576
    constexpr int MT = 2, NT = 4;              // warps 4x2

    extern __shared__ char smem[];
    const uint32_t sb = smem_to_u32(smem);

    const int tid  = threadIdx.x;
    const int warp = tid >> 5, lane = tid & 31;
    const int wm = warp >> 1, wn = warp & 1;
    const int rw = wm * 32;
    const int cw = wn * 32;

    const int z = blockIdx.z;                  // bh index
    const int bbz = z >> 4, hhz = z & 15;
    A   += (long long)z * TT * TT;
    Bhi += (long long)z * PP * TT;
    Blo += (long long)z * PP * TT;
    const long long coff = (long long)bbz * TT * DD + hhz * PP;

    const int row0 = blockIdx.y * 128;

    float acc[MT][NT][4];
#pragma unroll
    for (int i = 0; i < MT; i++)
#pragma unroll
        for (int j = 0; j < NT; j++)
#pragma unroll
            for (int q = 0; q < 4; q++) acc[i][j][q] = 0.f;

    const int nc = TT >> 5;                    // 64

    float4 ar[4];

    auto loadA = [&](int k0) {
#pragma unroll
        for (int l = 0; l < 4; l++) {
            int idx = tid + l * 256;
            int row = idx >> 3, seg = idx & 7;
            ar[l] = *(const float4*)(A + (long long)(row0 + row) * TT + k0 + seg * 4);
        }
    };
    auto convStoreA = [&](int buf) {
        uint32_t ah = sb + A_OFF + buf * ABUF;
        uint32_t al = ah + TILE_A;
#pragma unroll
        for (int l = 0; l < 4; l++) {
            int idx = tid + l * 256;
            int row = idx >> 3, seg = idx & 7;
            uint32_t sw = SMEM_SWIZZLE_64B((uint32_t)(row * 64 + seg * 8));
            float4 v = ar[l];
            __nv_bfloat162 h01 = __floats2bfloat162_rn(v.x, v.y);
            __nv_bfloat162 h23 = __floats2bfloat162_rn(v.z, v.w);
            float2 f01 = __bfloat1622float2(h01);
            float2 f23 = __bfloat1622float2(h23);
            __nv_bfloat162 l01 = __floats2bfloat162_rn(v.x - f01.x, v.y - f01.y);
            __nv_bfloat162 l23 = __floats2bfloat162_rn(v.z - f23.x, v.w - f23.y);
            uint2 hv, lv;
            hv.x = *(uint32_t*)&h01; hv.y = *(uint32_t*)&h23;
            lv.x = *(uint32_t*)&l01; lv.y = *(uint32_t*)&l23;
            *(uint2*)(smem + (ah - sb) + sw) = hv;
            *(uint2*)(smem + (al - sb) + sw) = lv;
        }
    };
    auto copyB = [&](int k0, int buf) {
        uint32_t bh = sb + buf * BSTAGE;
        uint32_t bl = bh + TILE_B;
        int idx = tid;                          // 256 threads cover 64 rows x 4 segs
        int row = idx >> 2, seg = idx & 3;
        long long g = (long long)row * TT + k0 + seg * 8;
        uint32_t sw = SMEM_SWIZZLE_64B((uint32_t)(row * 64 + seg * 16));
        cp16(bh + sw, Bhi + g);
        cp16(bl + sw, Blo + g);
    };

    // prologue
    loadA(0);
    convStoreA(0);
    loadA(32);
    copyB(0, 0);
    CP_COMMIT();
    copyB(32, 1);
    CP_COMMIT();
    __syncthreads();    // A buf0 visible to all warps

    const int lr = lane & 15;
    const int lk = lane >> 4;
    const int bnrow = (lane & 7) + ((lane >> 4) & 1) * 8;
    const int bkh   = (lane >> 3) & 1;

    for (int c = 0; c < nc; c++) {
        CP_WAIT1();
        __syncthreads();
        if (c + 2 < nc) copyB((c + 2) << 5, (c + 2) % 3);
        CP_COMMIT();
        if (c + 1 < nc) convStoreA((c + 1) & 1);   // regs hold chunk c+1
        if (c + 2 < nc) loadA((c + 2) << 5);

        uint32_t abase = sb + A_OFF + (c & 1) * ABUF;
        uint32_t bbase = sb + (c % 3) * BSTAGE;
#pragma unroll
        for (int ks = 0; ks < 2; ks++) {
            uint32_t afh[MT][4], afl[MT][4];
#pragma unroll
            for (int mt = 0; mt < MT; mt++) {
                uint32_t off = SMEM_SWIZZLE_64B((uint32_t)((rw + mt * 16 + lr) * 64 + ks * 32 + lk * 16));
                ldsm_x4(afh[mt], abase + off);
                ldsm_x4(afl[mt], abase + TILE_A + off);
            }
            uint32_t bfh[NT][2], bfl[NT][2];
#pragma unroll
            for (int g = 0; g < NT / 2; g++) {
                uint32_t off = SMEM_SWIZZLE_64B((uint32_t)((cw + g * 16 + bnrow) * 64 + ks * 32 + bkh * 16));
                uint32_t r4[4];
                ldsm_x4(r4, bbase + off);
                bfh[2 * g][0] = r4[0]; bfh[2 * g][1] = r4[1];
                bfh[2 * g + 1][0] = r4[2]; bfh[2 * g + 1][1] = r4[3];
                ldsm_x4(r4, bbase + TILE_B + off);
                bfl[2 * g][0] = r4[0]; bfl[2 * g][1] = r4[1];
                bfl[2 * g + 1][0] = r4[2]; bfl[2 * g + 1][1] = r4[3];
            }
#pragma unroll
            for (int mt = 0; mt < MT; mt++)
#pragma unroll
                for (int nt = 0; nt < NT; nt++) {
                    mma16816(acc[mt][nt], afh[mt], bfh[nt]);
                    mma16816(acc[mt][nt], afl[mt], bfh[nt]);
                    mma16816(acc[mt][nt], afh[mt], bfl[nt]);
                }
        }
    }
    __syncthreads();

    // ---- epilogue: hi/lo bf16 out ----
    constexpr int SP = BN + 4;
    float* stage = (float*)smem;
    {
        int qr = lane >> 2;
        int qc = (lane & 3) * 2;
#pragma unroll
        for (int mt = 0; mt < MT; mt++) {
            int r1 = rw + mt * 16 + qr;
            int r2 = r1 + 8;
#pragma unroll
            for (int nt = 0; nt < NT; nt++) {
                int cc = cw + nt * 8 + qc;
                stage[r1 * SP + cc]     = acc[mt][nt][0];
                stage[r1 * SP + cc + 1] = acc[mt][nt][1];
                stage[r2 * SP + cc]     = acc[mt][nt][2];
                stage[r2 * SP + cc + 1] = acc[mt][nt][3];
            }
        }
    }
    __syncthreads();
#pragma unroll
    for (int l = 0; l < BN / 8; l++) {
        int idx = tid + l * 256;
        int r2 = idx / (BN / 4);
        int c4 = (idx % (BN / 4)) * 4;
        int grow = row0 + r2;
        float4 v = *(float4*)&stage[r2 * SP + c4];
        long long o = coff + (long long)grow * DD + c4;
        __nv_bfloat162 h01 = __floats2bfloat162_rn(v.x, v.y);
        __nv_bfloat162 h23 = __floats2bfloat162_rn(v.z, v.w);
        float2 f01 = __bfloat1622float2(h01);
        float2 f23 = __bfloat1622float2(h23);
        __nv_bfloat162 l01 = __floats2bfloat162_rn(v.x - f01.x, v.y - f01.y);
        __nv_bfloat162 l23 = __floats2bfloat162_rn(v.z - f23.x, v.w - f23.y);
        uint2 hv, lv;
        hv.x = *(uint32_t*)&h01; hv.y = *(uint32_t*)&h23;
        lv.x = *(uint32_t*)&l01; lv.y = *(uint32_t*)&l23;
        *(uint2*)&Chi[o] = hv;
        *(uint2*)&Clo[o] = lv;
    }
}

// ---------------- host side ----------------
static const int SMEM_G = 98304;
static const int SMEM_AV = 57344;

extern "C" void kernel_launch(void* const* d_in, const int* in_sizes, int n_in,
                              void* d_out, int out_size) {
    const float* X      = (const float*)d_in[0];
    const float* WQ     = (const float*)d_in[1];
    const float* WK     = (const float*)d_in[2];
    const float* WV     = (const float*)d_in[3];
    const float* WO     = (const float*)d_in[4];
    const float* attn_g = (const float*)d_in[5];
    const float* attn_b = (const float*)d_in[6];
    const float* ff_g   = (const float*)d_in[7];
    const float* ff_b   = (const float*)d_in[8];
    const float* fW1    = (const float*)d_in[9];
    const float* fb1    = (const float*)d_in[10];
    const float* fW2    = (const float*)d_in[11];
    const float* fb2    = (const float*)d_in[12];

    float* out0 = (float*)d_out;                         // [B,T,D]
    float* attn = out0 + (long long)ROWS * DD;           // [B,H,T,T]

    cudaFuncSetAttribute(gemm_mma, cudaFuncAttributeMaxDynamicSharedMemorySize, SMEM_G);
    cudaFuncSetAttribute(gemm_av,  cudaFuncAttributeMaxDynamicSharedMemorySize, SMEM_AV);

    bf16 *wqkvT_h, *wqkvT_l, *woT_h, *woT_l, *fw1T_h, *fw1T_l, *fw2T_h, *fw2T_l;
    bf16 *nx_h, *nx_l, *qkv_h, *qkv_l, *vt_h, *vt_l;
    bf16 *nv_h, *nv_l, *pre_h, *pre_l, *hid_h, *hid_l;
    float *ss, *pre;
    cudaGetSymbolAddress((void**)&wqkvT_h, g_wqkvT_h); cudaGetSymbolAddress((void**)&wqkvT_l, g_wqkvT_l);
    cudaGetSymbolAddress((void**)&woT_h,  g_woT_h);    cudaGetSymbolAddress((void**)&woT_l,  g_woT_l);
    cudaGetSymbolAddress((void**)&fw1T_h, g_fw1T_h);   cudaGetSymbolAddress((void**)&fw1T_l, g_fw1T_l);
    cudaGetSymbolAddress((void**)&fw2T_h, g_fw2T_h);   cudaGetSymbolAddress((void**)&fw2T_l, g_fw2T_l);
    cudaGetSymbolAddress((void**)&nx_h,   g_nx_h);     cudaGetSymbolAddress((void**)&nx_l,   g_nx_l);
    cudaGetSymbolAddress((void**)&qkv_h,  g_qkv_h);    cudaGetSymbolAddress((void**)&qkv_l,  g_qkv_l);
    cudaGetSymbolAddress((void**)&vt_h,   g_vt_h);     cudaGetSymbolAddress((void**)&vt_l,   g_vt_l);
    cudaGetSymbolAddress((void**)&nv_h,   g_nv_h);     cudaGetSymbolAddress((void**)&nv_l,   g_nv_l);
    cudaGetSymbolAddress((void**)&pre_h,  g_pre_h);    cudaGetSymbolAddress((void**)&pre_l,  g_pre_l);
    cudaGetSymbolAddress((void**)&hid_h,  g_hid_h);    cudaGetSymbolAddress((void**)&hid_l,  g_hid_l);
    cudaGetSymbolAddress((void**)&ss,     g_ss);       cudaGetSymbolAddress((void**)&pre,    g_pre);

    dim3 tb32(32, 8);

    // 1. weight transposes + splits
    transpose_split<<<dim3(2, 32, 16), tb32>>>(WQ, wqkvT_h,                wqkvT_l,                64, DD, (long long)DD * PP, (long long)PP * DD);
    transpose_split<<<dim3(2, 32, 16), tb32>>>(WK, wqkvT_h + DD * DD,      wqkvT_l + DD * DD,      64, DD, (long long)DD * PP, (long long)PP * DD);
    transpose_split<<<dim3(2, 32, 16), tb32>>>(WV, wqkvT_h + 2 * DD * DD,  wqkvT_l + 2 * DD * DD,  64, DD, (long long)DD * PP, (long long)PP * DD);
    transpose_split<<<dim3(128, 32, 1), tb32>>>(fW1, fw1T_h, fw1T_l, FFD, DD, 0, 0);
    transpose_split<<<dim3(32, 128, 1), tb32>>>(fW2, fw2T_h, fw2T_l, DD, FFD, 0, 0);
    transpose_split<<<dim3(32, 32, 1),  tb32>>>(WO,  woT_h,  woT_l,  DD, DD, 0, 0);

    // 2. LN1 -> nx hi/lo
    ln_split_kernel<<<ROWS, 256>>>(X, attn_g, attn_b, nullptr, nullptr, nx_h, nx_l);

    // 3. QKV: [8192,1024] x [3072,1024]^T -> qkv hi/lo [8192,3072]
    gemm_mma<<<dim3(24, 64, 1), 256, SMEM_G>>>(
        nx_h, nx_l, wqkvT_h, wqkvT_l, DD, DD, DD, 3 * DD,
        1.f, nullptr, nullptr, 0, 0, nullptr, qkv_h, qkv_l,
        1, 0, 0, 0, 0, 0, 0);

    // 4. V^T per head
    vt_kernel<<<dim3(2, 64, 64), tb32>>>(qkv_h, qkv_l, vt_h, vt_l);

    // 5. scores (faithful index swap): rows = K-tokens, cols = Q-tokens
    gemm_mma<<<dim3(16, 16, 64), 256, SMEM_G>>>(
        qkv_h + DD, qkv_l + DD, qkv_h, qkv_l, PP, 3 * DD, 3 * DD, TT,
        0.125f, nullptr, nullptr, 0, 0, attn, nullptr, nullptr,
        16,
        (long long)TT * 3 * DD, PP,
        (long long)TT * 3 * DD, PP,
        16LL * TT * TT, (long long)TT * TT);

    // 6. softmax: warp-per-row, fp32 in-place
    softmax_kernel<<<BBATCH * HH * TT / 8, 256>>>(attn);

    // 7. AV: attn fp32 (split in-kernel, 3-pass) x V^T hi/lo -> nv hi/lo
    gemm_av<<<dim3(1, 16, 64), 256, SMEM_AV>>>(attn, vt_h, vt_l, nv_h, nv_l);

    // 8. WO: [8192,1024] x [1024,1024]^T -> ss fp32
    gemm_mma<<<dim3(8, 64, 1), 256, SMEM_G>>>(
        nv_h, nv_l, woT_h, woT_l, DD, DD, DD, DD,
        1.f, nullptr, nullptr, 0, 0, ss, nullptr, nullptr,
        1, 0, 0, 0, 0, 0, 0);

    // 9. pre_ff = X + LN(ss): fp32 + hi/lo
    ln_split_kernel<<<ROWS, 256>>>(ss, ff_g, ff_b, X, pre, pre_h, pre_l);

    // 10. FF1 + bias + gelu -> hid hi/lo
    gemm_mma<<<dim3(32, 64, 1), 256, SMEM_G>>>(
        pre_h, pre_l, fw1T_h, fw1T_l, DD, DD, DD, FFD,
        1.f, fb1, nullptr, 0, 1, nullptr, hid_h, hid_l,
        1, 0, 0, 0, 0, 0, 0);

    // 11. FF2 + bias + residual(pre) -> out0 fp32
    gemm_mma<<<dim3(8, 64, 1), 256, SMEM_G>>>(
        hid_h, hid_l, fw2T_h, fw2T_l, FFD, FFD, FFD, DD,
        1.f, fb2, pre, DD, 0, out0, nullptr, nullptr,
        1, 0, 0, 0, 0, 0, 0);
}

// round 13
// speedup vs baseline: 1.0719x; 1.0036x over previous
#include <cuda_runtime.h>
#include <cuda_bf16.h>
#include <cstdint>
#include <math.h>

// ---------------- problem constants ----------------
#define BBATCH 4
#define TT 2048
#define DD 1024
#define HH 16
#define PP 64
#define FFD 4096
#define ROWS (BBATCH*TT)          // 8192

typedef __nv_bfloat16 bf16;

#define SMEM_SWIZZLE_64B(off)  ((off) ^ (((off) >> 3) & 0x30))

__device__ __forceinline__ uint32_t smem_to_u32(const void* p) {
    uint32_t a;
    asm("{ .reg .u64 t; cvta.to.shared.u64 t, %1; cvt.u32.u64 %0, t; }" : "=r"(a) : "l"(p));
    return a;
}
__device__ __forceinline__ void cp16(uint32_t s, const void* g) {
    asm volatile("cp.async.cg.shared.global [%0], [%1], 16;" :: "r"(s), "l"(g));
}
#define CP_COMMIT() asm volatile("cp.async.commit_group;" ::: "memory")
#define CP_WAIT1()  asm volatile("cp.async.wait_group 1;" ::: "memory")

__device__ __forceinline__ void ldsm_x4(uint32_t* r, uint32_t addr) {
    asm volatile("ldmatrix.sync.aligned.m8n8.x4.shared.b16 {%0,%1,%2,%3}, [%4];"
                 : "=r"(r[0]), "=r"(r[1]), "=r"(r[2]), "=r"(r[3]) : "r"(addr));
}
__device__ __forceinline__ void mma16816(float* c, const uint32_t* a, const uint32_t* b) {
    asm volatile("mma.sync.aligned.m16n8k16.row.col.f32.bf16.bf16.f32 "
                 "{%0,%1,%2,%3}, {%4,%5,%6,%7}, {%8,%9}, {%0,%1,%2,%3};"
                 : "+f"(c[0]), "+f"(c[1]), "+f"(c[2]), "+f"(c[3])
                 : "r"(a[0]), "r"(a[1]), "r"(a[2]), "r"(a[3]), "r"(b[0]), "r"(b[1]));
}

// ---------------- scratch (static __device__, no allocation) ----------------
static __device__ bf16 g_wqkvT_h[3 * DD * DD], g_wqkvT_l[3 * DD * DD];     // [3072,1024]
static __device__ bf16 g_woT_h[DD * DD],       g_woT_l[DD * DD];           // [1024,1024]
static __device__ bf16 g_fw1T_h[FFD * DD],     g_fw1T_l[FFD * DD];         // [4096,1024]
static __device__ bf16 g_fw2T_h[DD * FFD],     g_fw2T_l[DD * FFD];         // [1024,4096]
static __device__ bf16 g_nx_h[ROWS * DD],      g_nx_l[ROWS * DD];
static __device__ bf16 g_qkv_h[ROWS * 3 * DD], g_qkv_l[ROWS * 3 * DD];
static __device__ bf16 g_vt_h[(size_t)BBATCH * HH * PP * TT], g_vt_l[(size_t)BBATCH * HH * PP * TT];
static __device__ bf16 g_nv_h[ROWS * DD],      g_nv_l[ROWS * DD];
static __device__ bf16 g_pre_h[ROWS * DD],     g_pre_l[ROWS * DD];
static __device__ bf16 g_hid_h[(size_t)ROWS * FFD], g_hid_l[(size_t)ROWS * FFD];
static __device__ float g_ss [ROWS * DD];
static __device__ float g_pre[ROWS * DD];

// ---------------- transpose + split: fp32 in [R,C] -> bf16 hi/lo [C,R] ----------------
__global__ void transpose_split(const float* __restrict__ in,
                                bf16* __restrict__ ohi, bf16* __restrict__ olo,
                                int ldin, int ldout, long long sIn, long long sOut) {
    __shared__ float t[32][33];
    const float* ip = in + (long long)blockIdx.z * sIn;
    long long ob = (long long)blockIdx.z * sOut;
    int r0 = blockIdx.y * 32, c0 = blockIdx.x * 32;
    int tx = threadIdx.x, ty = threadIdx.y;
#pragma unroll
    for (int j = 0; j < 32; j += 8)
        t[ty + j][tx] = ip[(long long)(r0 + ty + j) * ldin + c0 + tx];
    __syncthreads();
#pragma unroll
    for (int j = 0; j < 32; j += 8) {
        float v = t[tx][ty + j];
        bf16 h = __float2bfloat16(v);
        long long o = ob + (long long)(c0 + ty + j) * ldout + r0 + tx;
        ohi[o] = h;
        olo[o] = __float2bfloat16(v - __bfloat162float(h));
    }
}

// ---------------- V^T extraction (bf16 -> bf16 transpose per head) ----------------
__global__ void vt_kernel(const bf16* __restrict__ qhi, const bf16* __restrict__ qlo,
                          bf16* __restrict__ vhi, bf16* __restrict__ vlo) {
    __shared__ bf16 th[32][33], tl[32][33];
    int z = blockIdx.z, bb = z >> 4, hh = z & 15;
    const long long ib = (long long)bb * TT * (3 * DD) + 2 * DD + hh * PP;
    const long long ob = (long long)z * PP * TT;
    int t0 = blockIdx.y * 32, p0 = blockIdx.x * 32;
    int tx = threadIdx.x, ty = threadIdx.y;
#pragma unroll
    for (int j = 0; j < 32; j += 8) {
        long long g = ib + (long long)(t0 + ty + j) * (3 * DD) + p0 + tx;
        th[ty + j][tx] = qhi[g];
        tl[ty + j][tx] = qlo[g];
    }
    __syncthreads();
#pragma unroll
    for (int j = 0; j < 32; j += 8) {
        long long o = ob + (long long)(p0 + ty + j) * TT + t0 + tx;
        vhi[o] = th[tx][ty + j];
        vlo[o] = tl[tx][ty + j];
    }
}

// ---------------- layernorm (+opt residual), float4 path ----------------
__global__ void ln_split_kernel(const float* __restrict__ x,
                                const float* __restrict__ gamma,
                                const float* __restrict__ beta,
                                const float* __restrict__ residual,
                                float* __restrict__ outf,
                                bf16* __restrict__ ohi, bf16* __restrict__ olo) {
    int row = blockIdx.x;
    int tid = threadIdx.x;               // 256 threads, 4 contiguous elems each
    long long rb = (long long)row * DD;
    float4 v = *(const float4*)(x + rb + tid * 4);
    float s  = v.x + v.y + v.z + v.w;
    float sq = v.x * v.x + v.y * v.y + v.z * v.z + v.w * v.w;
    __shared__ float red[2][32];
    for (int o = 16; o > 0; o >>= 1) {
        s  += __shfl_xor_sync(0xffffffff, s, o);
        sq += __shfl_xor_sync(0xffffffff, sq, o);
    }
    int wid = tid >> 5, lid = tid & 31;
    if (lid == 0) { red[0][wid] = s; red[1][wid] = sq; }
    __syncthreads();
    if (wid == 0) {
        s = red[0][lid & 7]; sq = red[1][lid & 7];
        for (int o = 4; o > 0; o >>= 1) {
            s  += __shfl_xor_sync(0xffffffff, s, o);
            sq += __shfl_xor_sync(0xffffffff, sq, o);
        }
        if (lid == 0) { red[0][0] = s; red[1][0] = sq; }
    }
    __syncthreads();
    float mean = red[0][0] * (1.0f / DD);
    float var  = red[1][0] * (1.0f / DD) - mean * mean;
    float rstd = rsqrtf(var + 1e-5f);
    float4 gm = *(const float4*)(gamma + tid * 4);
    float4 bt = *(const float4*)(beta  + tid * 4);
    float o0 = (v.x - mean) * rstd * gm.x + bt.x;
    float o1 = (v.y - mean) * rstd * gm.y + bt.y;
    float o2 = (v.z - mean) * rstd * gm.z + bt.z;
    float o3 = (v.w - mean) * rstd * gm.w + bt.w;
    if (residual) {
        float4 rr = *(const float4*)(residual + rb + tid * 4);
        o0 += rr.x; o1 += rr.y; o2 += rr.z; o3 += rr.w;
    }
    if (outf) {
        float4 ov = make_float4(o0, o1, o2, o3);
        *(float4*)(outf + rb + tid * 4) = ov;
    }
    __nv_bfloat162 h01 = __floats2bfloat162_rn(o0, o1);
    __nv_bfloat162 h23 = __floats2bfloat162_rn(o2, o3);
    float2 f01 = __bfloat1622float2(h01);
    float2 f23 = __bfloat1622float2(h23);
    __nv_bfloat162 l01 = __floats2bfloat162_rn(o0 - f01.x, o1 - f01.y);
    __nv_bfloat162 l23 = __floats2bfloat162_rn(o2 - f23.x, o3 - f23.y);
    uint2 hv, lv;
    hv.x = *(uint32_t*)&h01; hv.y = *(uint32_t*)&h23;
    lv.x = *(uint32_t*)&l01; lv.y = *(uint32_t*)&l23;
    *(uint2*)(ohi + rb + tid * 4) = hv;
    *(uint2*)(olo + rb + tid * 4) = lv;
}

// ---------------- softmax: one WARP per row of 2048, fp32 in-place ----------------
__global__ __launch_bounds__(256)
void softmax_kernel(float* __restrict__ a) {
    int warp = threadIdx.x >> 5, lane = threadIdx.x & 31;
    long long row = (long long)blockIdx.x * 8 + warp;
    float4* r4 = (float4*)(a + row * (long long)TT);
    float4 v[16];
#pragma unroll
    for (int i = 0; i < 16; i++) v[i] = r4[lane + i * 32];
    float mx = -1e30f;
#pragma unroll
    for (int i = 0; i < 16; i++) {
        mx = fmaxf(mx, fmaxf(fmaxf(v[i].x, v[i].y), fmaxf(v[i].z, v[i].w)));
    }
#pragma unroll
    for (int o = 16; o > 0; o >>= 1) mx = fmaxf(mx, __shfl_xor_sync(0xffffffff, mx, o));
    float s = 0.f;
#pragma unroll
    for (int i = 0; i < 16; i++) {
        v[i].x = __expf(v[i].x - mx); s += v[i].x;
        v[i].y = __expf(v[i].y - mx); s += v[i].y;
        v[i].z = __expf(v[i].z - mx); s += v[i].z;
        v[i].w = __expf(v[i].w - mx); s += v[i].w;
    }
#pragma unroll
    for (int o = 16; o > 0; o >>= 1) s += __shfl_xor_sync(0xffffffff, s, o);
    float inv = 1.0f / s;
#pragma unroll
    for (int i = 0; i < 16; i++) {
        v[i].x *= inv; v[i].y *= inv; v[i].z *= inv; v[i].w *= inv;
        r4[lane + i * 32] = v[i];
    }
}

// =====================================================================
// Generic split-bf16 GEMM on mma.sync.  C = alpha * A@B^T.
// A [M,K] hi/lo, B [N,K] hi/lo, K-major bf16.
// Passes: Ahi*Bhi + Alo*Bhi + Ahi*Blo, fp32 accum.
// 256 threads, tile 128x128, BK=32 (64B rows, SW64), 3-stage cp.async,
// 2 CTAs/SM (128-reg cap).  Mainloop sequences the 3 passes so only one
// extra fragment set is live at a time (peak ~104 regs; avoids spills):
//   load Ahi,Bhi -> pass1; load Alo -> pass2; load Blo over Bhi -> pass3.
// =====================================================================
__global__ __launch_bounds__(256, 2)
void gemm_mma(const bf16* __restrict__ Ahi, const bf16* __restrict__ Alo,
              const bf16* __restrict__ Bhi, const bf16* __restrict__ Blo,
              int K, int lda, int ldb, int ldc,
              float alpha,
              const float* __restrict__ bias,
              const float* __restrict__ residual, int ldres,
              int doGelu,
              float* __restrict__ Cf,
              bf16* __restrict__ Chi, bf16* __restrict__ Clo,
              int hdiv,
              long long sAb, long long sAh,
              long long sBb, long long sBh,
              long long sCb, long long sCh) {
    constexpr int BN = 128;
    constexpr int TILE_A = 128 * 64;
    constexpr int TILE_B = BN * 64;
    constexpr int STAGE  = 2 * TILE_A + 2 * TILE_B;
    constexpr int MT = 4, NT = 4;          // warps 2x4, warp tile 64x32

    extern __shared__ char smem[];
    const uint32_t sb = smem_to_u32(smem);

    const int tid  = threadIdx.x;
    const int warp = tid >> 5, lane = tid & 31;
    const int wm = warp >> 2, wn = warp & 3;
    const int rw = wm * 64;
    const int cw = wn * 32;

    int z = blockIdx.z;
    int bbz = z / hdiv, hhz = z % hdiv;
    Ahi += bbz * sAb + hhz * sAh;  Alo += bbz * sAb + hhz * sAh;
    Bhi += bbz * sBb + hhz * sBh;  Blo += bbz * sBb + hhz * sBh;
    const long long coff = bbz * sCb + hhz * sCh;

    const int row0 = blockIdx.y * 128;
    const int col0 = blockIdx.x * BN;

    float acc[MT][NT][4];
#pragma unroll
    for (int i = 0; i < MT; i++)
#pragma unroll
        for (int j = 0; j < NT; j++)
#pragma unroll
            for (int q = 0; q < 4; q++) acc[i][j][q] = 0.f;

    const int nc = K >> 5;

    auto copy_chunk = [&](int k0, int buf) {
        uint32_t ah = sb + buf * STAGE;
        uint32_t bh = ah + 2 * TILE_A;
        uint32_t bl = bh + TILE_B;
#pragma unroll
        for (int l = 0; l < 2; l++) {
            int idx = tid + l * 256;
            int row = idx >> 2, seg = idx & 3;
            long long g = (long long)(row0 + row) * lda + k0 + seg * 8;
            uint32_t sw = SMEM_SWIZZLE_64B((uint32_t)(row * 64 + seg * 16));
            cp16(ah + sw, Ahi + g);
            cp16(ah + TILE_A + sw, Alo + g);
        }
#pragma unroll
        for (int l = 0; l < 2; l++) {
            int idx = tid + l * 256;
            int row = idx >> 2, seg = idx & 3;
            long long g = (long long)(col0 + row) * ldb + k0 + seg * 8;
            uint32_t sw = SMEM_SWIZZLE_64B((uint32_t)(row * 64 + seg * 16));
            cp16(bh + sw, Bhi + g);
            cp16(bl + sw, Blo + g);
        }
    };

    copy_chunk(0, 0);
    CP_COMMIT();
    if (nc > 1) copy_chunk(32, 1);
    CP_COMMIT();

    const int lr = lane & 15;
    const int lk = lane >> 4;
    const int bnrow = (lane & 7) + ((lane >> 4) & 1) * 8;
    const int bkh   = (lane >> 3) & 1;

    for (int c = 0; c < nc; c++) {
        CP_WAIT1();
        __syncthreads();
        if (c + 2 < nc) copy_chunk((c + 2) << 5, (c + 2) % 3);
        CP_COMMIT();

        uint32_t abase = sb + (c % 3) * STAGE;
        uint32_t bbase = abase + 2 * TILE_A;
#pragma unroll
        for (int ks = 0; ks < 2; ks++) {
            uint32_t af[MT][4];   // A fragments (hi first, then reused per pass)
            uint32_t af2[MT][4];  // A-lo fragments
            uint32_t bf[NT][2];   // B fragments (hi, then overwritten with lo)

            // ---- load A-hi + B-hi ----
#pragma unroll
            for (int mt = 0; mt < MT; mt++) {
                uint32_t off = SMEM_SWIZZLE_64B((uint32_t)((rw + mt * 16 + lr) * 64 + ks * 32 + lk * 16));
                ldsm_x4(af[mt], abase + off);
            }
#pragma unroll
            for (int g = 0; g < NT / 2; g++) {
                uint32_t off = SMEM_SWIZZLE_64B((uint32_t)((cw + g * 16 + bnrow) * 64 + ks * 32 + bkh * 16));
                uint32_t r4[4];
                ldsm_x4(r4, bbase + off);
                bf[2 * g][0] = r4[0]; bf[2 * g][1] = r4[1];
                bf[2 * g + 1][0] = r4[2]; bf[2 * g + 1][1] = r4[3];
            }
            // ---- pass 1: Ahi * Bhi ----
#pragma unroll
            for (int mt = 0; mt < MT; mt++)
#pragma unroll
                for (int nt = 0; nt < NT; nt++)
                    mma16816(acc[mt][nt], af[mt], bf[nt]);

            // ---- load A-lo; pass 2: Alo * Bhi ----
#pragma unroll
            for (int mt = 0; mt < MT; mt++) {
                uint32_t off = SMEM_SWIZZLE_64B((uint32_t)((rw + mt * 16 + lr) * 64 + ks * 32 + lk * 16));
                ldsm_x4(af2[mt], abase + TILE_A + off);
            }
#pragma unroll
            for (int mt = 0; mt < MT; mt++)
#pragma unroll
                for (int nt = 0; nt < NT; nt++)
                    mma16816(acc[mt][nt], af2[mt], bf[nt]);

            // ---- load B-lo (over bf); pass 3: Ahi * Blo ----
#pragma unroll
            for (int g = 0; g < NT / 2; g++) {
                uint32_t off = SMEM_SWIZZLE_64B((uint32_t)((cw + g * 16 + bnrow) * 64 + ks * 32 + bkh * 16));
                uint32_t r4[4];
                ldsm_x4(r4, bbase + TILE_B + off);
                bf[2 * g][0] = r4[0]; bf[2 * g][1] = r4[1];
                bf[2 * g + 1][0] = r4[2]; bf[2 * g + 1][1] = r4[3];
            }
#pragma unroll
            for (int mt = 0; mt < MT; mt++)
#pragma unroll
                for (int nt = 0; nt < NT; nt++)
                    mma16816(acc[mt][nt], af[mt], bf[nt]);
        }
    }
    __syncthreads();

    // ---- epilogue ----
    constexpr int SP = BN + 4;
    float* stage = (float*)smem;
    {
        int qr = lane >> 2;
        int qc = (lane & 3) * 2;
#pragma unroll
        for (int mt = 0; mt < MT; mt++) {
            int r1 = rw + mt * 16 + qr;
            int r2 = r1 + 8;
#pragma unroll
            for (int nt = 0; nt < NT; nt++) {
                int cc = cw + nt * 8 + qc;
                stage[r1 * SP + cc]     = acc[mt][nt][0];
                stage[r1 * SP + cc + 1] = acc[mt][nt][1];
                stage[r2 * SP + cc]     = acc[mt][nt][2];
                stage[r2 * SP + cc + 1] = acc[mt][nt][3];
            }
        }
    }
    __syncthreads();
#pragma unroll
    for (int l = 0; l < BN / 8; l++) {
        int idx = tid + l * 256;
        int r2 = idx / (BN / 4);
        int c4 = (idx % (BN / 4)) * 4;
        int grow = row0 + r2;
        int gcol = col0 + c4;
        float4 v = *(float4*)&stage[r2 * SP + c4];
        float* vp = (float*)&v;
#pragma unroll
        for (int j = 0; j < 4; j++) {
            float x = vp[j] * alpha;
            if (bias) x += bias[gcol + j];
            if (doGelu) x = 0.5f * x * (1.0f + erff(x * 0.70710678118654752f));
            if (residual) x += residual[(long long)grow * ldres + gcol + j];
            vp[j] = x;
        }
        long long o = coff + (long long)grow * ldc + gcol;
        if (Cf) *(float4*)&Cf[o] = v;
        if (Chi) {
            __nv_bfloat162 h01 = __floats2bfloat162_rn(vp[0], vp[1]);
            __nv_bfloat162 h23 = __floats2bfloat162_rn(vp[2], vp[3]);
            float2 f01 = __bfloat1622float2(h01);
            float2 f23 = __bfloat1622float2(h23);
            __nv_bfloat162 l01 = __floats2bfloat162_rn(vp[0] - f01.x, vp[1] - f01.y);
            __nv_bfloat162 l23 = __floats2bfloat162_rn(vp[2] - f23.x, vp[3] - f23.y);
            uint2 hv, lv;
            hv.x = *(uint32_t*)&h01; hv.y = *(uint32_t*)&h23;
            lv.x = *(uint32_t*)&l01; lv.y = *(uint32_t*)&l23;
            *(uint2*)&Chi[o] = hv;
            *(uint2*)&Clo[o] = lv;
        }
    }
}

// =====================================================================
// AV GEMM: A = attn fp32 [T,T] row-major, split to bf16 hi/lo IN-KERNEL.
// B = V^T hi/lo bf16 [P=64, T] K-major.  nv = A @ B^T, full 3-pass.
// =====================================================================
__global__ __launch_bounds__(256, 2)
void gemm_av(const float* __restrict__ A,
             const bf16* __restrict__ Bhi, const bf16* __restrict__ Blo,
             bf16* __restrict__ Chi, bf16* __restrict__ Clo) {
    constexpr int BN = 64;
    constexpr int TILE_B = BN * 64;            // 4096 B
    constexpr int BSTAGE = 2 * TILE_B;         // 8192
    constexpr int TILE_A = 128 * 64;           // 8192 (bf16 tile bytes)
    constexpr int ABUF   = 2 * TILE_A;         // hi+lo = 16384
    constexpr int A_OFF  = 3 * BSTAGE;         // 24576
    constexpr int MT = 2, NT = 4;              // warps 4x2

    extern __shared__ char smem[];
    const uint32_t sb = smem_to_u32(smem);

    const int tid  = threadIdx.x;
    const int warp = tid >> 5, lane = tid & 31;
    const int wm = warp >> 1, wn = warp & 1;
    const int rw = wm * 32;
    const int cw = wn * 32;

    const int z = blockIdx.z;                  // bh index
    const int bbz = z >> 4, hhz = z & 15;
    A   += (long long)z * TT * TT;
    Bhi += (long long)z * PP * TT;
    Blo += (long long)z * PP * TT;
    const long long coff = (long long)bbz * TT * DD + hhz * PP;

    const int row0 = blockIdx.y * 128;

    float acc[MT][NT][4];
#pragma unroll
    for (int i = 0; i < MT; i++)
#pragma unroll
        for (int j = 0; j < NT; j++)
#pragma unroll
            for (int q = 0; q < 4; q++) acc[i][j][q] = 0.f;

    const int nc = TT >> 5;                    // 64

    float4 ar[4];

    auto loadA = [&](int k0) {
#pragma unroll
        for (int l = 0; l < 4; l++) {
            int idx = tid + l * 256;
            int row = idx >> 3, seg = idx & 7;
            ar[l] = *(const float4*)(A + (long long)(row0 + row) * TT + k0 + seg * 4);
        }
    };
    auto convStoreA = [&](int buf) {
        uint32_t ah = sb + A_OFF + buf * ABUF;
        uint32_t al = ah + TILE_A;
#pragma unroll
        for (int l = 0; l < 4; l++) {
            int idx = tid + l * 256;
            int row = idx >> 3, seg = idx & 7;
            uint32_t sw = SMEM_SWIZZLE_64B((uint32_t)(row * 64 + seg * 8));
            float4 v = ar[l];
            __nv_bfloat162 h01 = __floats2bfloat162_rn(v.x, v.y);
            __nv_bfloat162 h23 = __floats2bfloat162_rn(v.z, v.w);
            float2 f01 = __bfloat1622float2(h01);
            float2 f23 = __bfloat1622float2(h23);
            __nv_bfloat162 l01 = __floats2bfloat162_rn(v.x - f01.x, v.y - f01.y);
            __nv_bfloat162 l23 = __floats2bfloat162_rn(v.z - f23.x, v.w - f23.y);
            uint2 hv, lv;
            hv.x = *(uint32_t*)&h01; hv.y = *(uint32_t*)&h23;
            lv.x = *(uint32_t*)&l01; lv.y = *(uint32_t*)&l23;
            *(uint2*)(smem + (ah - sb) + sw) = hv;
            *(uint2*)(smem + (al - sb) + sw) = lv;
        }
    };
    auto copyB = [&](int k0, int buf) {
        uint32_t bh = sb + buf * BSTAGE;
        uint32_t bl = bh + TILE_B;
        int idx = tid;
        int row = idx >> 2, seg = idx & 3;
        long long g = (long long)row * TT + k0 + seg * 8;
        uint32_t sw = SMEM_SWIZZLE_64B((uint32_t)(row * 64 + seg * 16));
        cp16(bh + sw, Bhi + g);
        cp16(bl + sw, Blo + g);
    };

    // prologue
    loadA(0);
    convStoreA(0);
    loadA(32);
    copyB(0, 0);
    CP_COMMIT();
    copyB(32, 1);
    CP_COMMIT();
    __syncthreads();

    const int lr = lane & 15;
    const int lk = lane >> 4;
    const int bnrow = (lane & 7) + ((lane >> 4) & 1) * 8;
    const int bkh   = (lane >> 3) & 1;

    for (int c = 0; c < nc; c++) {
        CP_WAIT1();
        __syncthreads();
        if (c + 2 < nc) copyB((c + 2) << 5, (c + 2) % 3);
        CP_COMMIT();
        if (c + 1 < nc) convStoreA((c + 1) & 1);
        if (c + 2 < nc) loadA((c + 2) << 5);

        uint32_t abase = sb + A_OFF + (c & 1) * ABUF;
        uint32_t bbase = sb + (c % 3) * BSTAGE;
#pragma unroll
        for (int ks = 0; ks < 2; ks++) {
            uint32_t af[MT][4], af2[MT][4];
            uint32_t bf[NT][2];
#pragma unroll
            for (int mt = 0; mt < MT; mt++) {
                uint32_t off = SMEM_SWIZZLE_64B((uint32_t)((rw + mt * 16 + lr) * 64 + ks * 32 + lk * 16));
                ldsm_x4(af[mt], abase + off);
            }
#pragma unroll
            for (int g = 0; g < NT / 2; g++) {
                uint32_t off = SMEM_SWIZZLE_64B((uint32_t)((cw + g * 16 + bnrow) * 64 + ks * 32 + bkh * 16));
                uint32_t r4[4];
                ldsm_x4(r4, bbase + off);
                bf[2 * g][0] = r4[0]; bf[2 * g][1] = r4[1];
                bf[2 * g + 1][0] = r4[2]; bf[2 * g + 1][1] = r4[3];
            }
#pragma unroll
            for (int mt = 0; mt < MT; mt++)
#pragma unroll
                for (int nt = 0; nt < NT; nt++)
                    mma16816(acc[mt][nt], af[mt], bf[nt]);
#pragma unroll
            for (int mt = 0; mt < MT; mt++) {
                uint32_t off = SMEM_SWIZZLE_64B((uint32_t)((rw + mt * 16 + lr) * 64 + ks * 32 + lk * 16));
                ldsm_x4(af2[mt], abase + TILE_A + off);
            }
#pragma unroll
            for (int mt = 0; mt < MT; mt++)
#pragma unroll
                for (int nt = 0; nt < NT; nt++)
                    mma16816(acc[mt][nt], af2[mt], bf[nt]);
#pragma unroll
            for (int g = 0; g < NT / 2; g++) {
                uint32_t off = SMEM_SWIZZLE_64B((uint32_t)((cw + g * 16 + bnrow) * 64 + ks * 32 + bkh * 16));
                uint32_t r4[4];
                ldsm_x4(r4, bbase + TILE_B + off);
                bf[2 * g][0] = r4[0]; bf[2 * g][1] = r4[1];
                bf[2 * g + 1][0] = r4[2]; bf[2 * g + 1][1] = r4[3];
            }
#pragma unroll
            for (int mt = 0; mt < MT; mt++)
#pragma unroll
                for (int nt = 0; nt < NT; nt++)
                    mma16816(acc[mt][nt], af[mt], bf[nt]);
        }
    }
    __syncthreads();

    // ---- epilogue: hi/lo bf16 out ----
    constexpr int SP = BN + 4;
    float* stage = (float*)smem;
    {
        int qr = lane >> 2;
        int qc = (lane & 3) * 2;
#pragma unroll
        for (int mt = 0; mt < MT; mt++) {
            int r1 = rw + mt * 16 + qr;
            int r2 = r1 + 8;
#pragma unroll
            for (int nt = 0; nt < NT; nt++) {
                int cc = cw + nt * 8 + qc;
                stage[r1 * SP + cc]     = acc[mt][nt][0];
                stage[r1 * SP + cc + 1] = acc[mt][nt][1];
                stage[r2 * SP + cc]     = acc[mt][nt][2];
                stage[r2 * SP + cc + 1] = acc[mt][nt][3];
            }
        }
    }
    __syncthreads();
#pragma unroll
    for (int l = 0; l < BN / 8; l++) {
        int idx = tid + l * 256;
        int r2 = idx / (BN / 4);
        int c4 = (idx % (BN / 4)) * 4;
        int grow = row0 + r2;
        float4 v = *(float4*)&stage[r2 * SP + c4];
        long long o = coff + (long long)grow * DD + c4;
        __nv_bfloat162 h01 = __floats2bfloat162_rn(v.x, v.y);
        __nv_bfloat162 h23 = __floats2bfloat162_rn(v.z, v.w);
        float2 f01 = __bfloat1622float2(h01);
        float2 f23 = __bfloat1622float2(h23);
        __nv_bfloat162 l01 = __floats2bfloat162_rn(v.x - f01.x, v.y - f01.y);
        __nv_bfloat162 l23 = __floats2bfloat162_rn(v.z - f23.x, v.w - f23.y);
        uint2 hv, lv;
        hv.x = *(uint32_t*)&h01; hv.y = *(uint32_t*)&h23;
        lv.x = *(uint32_t*)&l01; lv.y = *(uint32_t*)&l23;
        *(uint2*)&Chi[o] = hv;
        *(uint2*)&Clo[o] = lv;
    }
}

// ---------------- host side ----------------
static const int SMEM_G = 98304;
static const int SMEM_AV = 57344;

extern "C" void kernel_launch(void* const* d_in, const int* in_sizes, int n_in,
                              void* d_out, int out_size) {
    const float* X      = (const float*)d_in[0];
    const float* WQ     = (const float*)d_in[1];
    const float* WK     = (const float*)d_in[2];
    const float* WV     = (const float*)d_in[3];
    const float* WO     = (const float*)d_in[4];
    const float* attn_g = (const float*)d_in[5];
    const float* attn_b = (const float*)d_in[6];
    const float* ff_g   = (const float*)d_in[7];
    const float* ff_b   = (const float*)d_in[8];
    const float* fW1    = (const float*)d_in[9];
    const float* fb1    = (const float*)d_in[10];
    const float* fW2    = (const float*)d_in[11];
    const float* fb2    = (const float*)d_in[12];

    float* out0 = (float*)d_out;                         // [B,T,D]
    float* attn = out0 + (long long)ROWS * DD;           // [B,H,T,T]

    cudaFuncSetAttribute(gemm_mma, cudaFuncAttributeMaxDynamicSharedMemorySize, SMEM_G);
    cudaFuncSetAttribute(gemm_av,  cudaFuncAttributeMaxDynamicSharedMemorySize, SMEM_AV);

    bf16 *wqkvT_h, *wqkvT_l, *woT_h, *woT_l, *fw1T_h, *fw1T_l, *fw2T_h, *fw2T_l;
    bf16 *nx_h, *nx_l, *qkv_h, *qkv_l, *vt_h, *vt_l;
    bf16 *nv_h, *nv_l, *pre_h, *pre_l, *hid_h, *hid_l;
    float *ss, *pre;
    cudaGetSymbolAddress((void**)&wqkvT_h, g_wqkvT_h); cudaGetSymbolAddress((void**)&wqkvT_l, g_wqkvT_l);
    cudaGetSymbolAddress((void**)&woT_h,  g_woT_h);    cudaGetSymbolAddress((void**)&woT_l,  g_woT_l);
    cudaGetSymbolAddress((void**)&fw1T_h, g_fw1T_h);   cudaGetSymbolAddress((void**)&fw1T_l, g_fw1T_l);
    cudaGetSymbolAddress((void**)&fw2T_h, g_fw2T_h);   cudaGetSymbolAddress((void**)&fw2T_l, g_fw2T_l);
    cudaGetSymbolAddress((void**)&nx_h,   g_nx_h);     cudaGetSymbolAddress((void**)&nx_l,   g_nx_l);
    cudaGetSymbolAddress((void**)&qkv_h,  g_qkv_h);    cudaGetSymbolAddress((void**)&qkv_l,  g_qkv_l);
    cudaGetSymbolAddress((void**)&vt_h,   g_vt_h);     cudaGetSymbolAddress((void**)&vt_l,   g_vt_l);
    cudaGetSymbolAddress((void**)&nv_h,   g_nv_h);     cudaGetSymbolAddress((void**)&nv_l,   g_nv_l);
    cudaGetSymbolAddress((void**)&pre_h,  g_pre_h);    cudaGetSymbolAddress((void**)&pre_l,  g_pre_l);
    cudaGetSymbolAddress((void**)&hid_h,  g_hid_h);    cudaGetSymbolAddress((void**)&hid_l,  g_hid_l);
    cudaGetSymbolAddress((void**)&ss,     g_ss);       cudaGetSymbolAddress((void**)&pre,    g_pre);

    dim3 tb32(32, 8);

    // Launch order arranged so ncu (-s 5 -c 1) captures the QKV gemm_mma.
    // 0. LN1 -> nx hi/lo
    ln_split_kernel<<<ROWS, 256>>>(X, attn_g, attn_b, nullptr, nullptr, nx_h, nx_l);
    // 1-3. WQ/WK/WV transposes
    transpose_split<<<dim3(2, 32, 16), tb32>>>(WQ, wqkvT_h,                wqkvT_l,                64, DD, (long long)DD * PP, (long long)PP * DD);
    transpose_split<<<dim3(2, 32, 16), tb32>>>(WK, wqkvT_h + DD * DD,      wqkvT_l + DD * DD,      64, DD, (long long)DD * PP, (long long)PP * DD);
    transpose_split<<<dim3(2, 32, 16), tb32>>>(WV, wqkvT_h + 2 * DD * DD,  wqkvT_l + 2 * DD * DD,  64, DD, (long long)DD * PP, (long long)PP * DD);
    // 4. fW1 transpose
    transpose_split<<<dim3(128, 32, 1), tb32>>>(fW1, fw1T_h, fw1T_l, FFD, DD, 0, 0);
    // 5. QKV gemm  <-- ncu capture target
    gemm_mma<<<dim3(24, 64, 1), 256, SMEM_G>>>(
        nx_h, nx_l, wqkvT_h, wqkvT_l, DD, DD, DD, 3 * DD,
        1.f, nullptr, nullptr, 0, 0, nullptr, qkv_h, qkv_l,
        1, 0, 0, 0, 0, 0, 0);
    // 6-7. remaining weight transposes
    transpose_split<<<dim3(32, 128, 1), tb32>>>(fW2, fw2T_h, fw2T_l, DD, FFD, 0, 0);
    transpose_split<<<dim3(32, 32, 1),  tb32>>>(WO,  woT_h,  woT_l,  DD, DD, 0, 0);
    // 8. V^T per head
    vt_kernel<<<dim3(2, 64, 64), tb32>>>(qkv_h, qkv_l, vt_h, vt_l);
    // 9. scores (faithful index swap): rows = K-tokens, cols = Q-tokens
    gemm_mma<<<dim3(16, 16, 64), 256, SMEM_G>>>(
        qkv_h + DD, qkv_l + DD, qkv_h, qkv_l, PP, 3 * DD, 3 * DD, TT,
        0.125f, nullptr, nullptr, 0, 0, attn, nullptr, nullptr,
        16,
        (long long)TT * 3 * DD, PP,
        (long long)TT * 3 * DD, PP,
        16LL * TT * TT, (long long)TT * TT);
    // 10. softmax: warp-per-row, fp32 in-place
    softmax_kernel<<<BBATCH * HH * TT / 8, 256>>>(attn);
    // 11. AV: attn fp32 (split in-kernel, 3-pass) x V^T hi/lo -> nv hi/lo
    gemm_av<<<dim3(1, 16, 64), 256, SMEM_AV>>>(attn, vt_h, vt_l, nv_h, nv_l);
    // 12. WO: [8192,1024] x [1024,1024]^T -> ss fp32
    gemm_mma<<<dim3(8, 64, 1), 256, SMEM_G>>>(
        nv_h, nv_l, woT_h, woT_l, DD, DD, DD, DD,
        1.f, nullptr, nullptr, 0, 0, ss, nullptr, nullptr,
        1, 0, 0, 0, 0, 0, 0);
    // 13. pre_ff = X + LN(ss): fp32 + hi/lo
    ln_split_kernel<<<ROWS, 256>>>(ss, ff_g, ff_b, X, pre, pre_h, pre_l);
    // 14. FF1 + bias + gelu -> hid hi/lo
    gemm_mma<<<dim3(32, 64, 1), 256, SMEM_G>>>(
        pre_h, pre_l, fw1T_h, fw1T_l, DD, DD, DD, FFD,
        1.f, fb1, nullptr, 0, 1, nullptr, hid_h, hid_l,
        1, 0, 0, 0, 0, 0, 0);
    // 15. FF2 + bias + residual(pre) -> out0 fp32
    gemm_mma<<<dim3(8, 64, 1), 256, SMEM_G>>>(
        hid_h, hid_l, fw2T_h, fw2T_l, FFD, FFD, FFD, DD,
        1.f, fb2, pre, DD, 0, out0, nullptr, nullptr,
        1, 0, 0, 0, 0, 0, 0);
}